// round 4
// baseline (speedup 1.0000x reference)
#include <cuda_runtime.h>
#include <cuda_fp16.h>
#include <math.h>
#include <stdint.h>

#define D_MODEL 1024
#define T_TOT   2052
#define MPAD    2176   // 17*128
#define L_SEQ   2048
#define NP      4
#define NHEADS  16
#define HD      64
#define WIN     128

// ---------------- scratch (device globals: allocation-free) ----------------
__device__ float g_QKV[3][T_TOT * D_MODEL];   // pre-conv Q,K,V (fp32)
__device__ float g_QKVc[3][T_TOT * D_MODEL];  // post conv+silu(+norm)
__device__ __half g_xp_h[MPAD * D_MODEL];
__device__ __half g_xp_l[MPAD * D_MODEL];
__device__ __half g_w_h[4][D_MODEL * D_MODEL];
__device__ __half g_w_l[4][D_MODEL * D_MODEL];
__device__ __half g_at_h[L_SEQ * D_MODEL];
__device__ __half g_at_l[L_SEQ * D_MODEL];

// ---------------- helpers ----------------
__device__ __forceinline__ uint32_t smem_u32(const void* p) {
    uint32_t a;
    asm("{ .reg .u64 t; cvta.to.shared.u64 t, %1; cvt.u32.u64 %0, t; }" : "=r"(a) : "l"(p));
    return a;
}

#define LDSM4(R0, R1, R2, R3, ADDR) \
    asm volatile("ldmatrix.sync.aligned.m8n8.x4.shared.b16 {%0,%1,%2,%3}, [%4];" \
                 : "=r"(R0), "=r"(R1), "=r"(R2), "=r"(R3) : "r"(ADDR))

#define MMA16816(D, A0, A1, A2, A3, B0, B1) \
    asm volatile("mma.sync.aligned.m16n8k16.row.col.f32.f16.f16.f32 " \
                 "{%0,%1,%2,%3}, {%4,%5,%6,%7}, {%8,%9}, {%0,%1,%2,%3};" \
                 : "+f"((D)[0]), "+f"((D)[1]), "+f"((D)[2]), "+f"((D)[3]) \
                 : "r"(A0), "r"(A1), "r"(A2), "r"(A3), "r"(B0), "r"(B1))

#define CP_ASYNC16(S, G) \
    asm volatile("cp.async.cg.shared.global [%0], [%1], 16;" :: "r"(S), "l"(G))
#define CP_COMMIT()  asm volatile("cp.async.commit_group;" ::: "memory")
#define CP_WAIT1()   asm volatile("cp.async.wait_group 1;" ::: "memory")

// fp16 hi/lo split of a float4 -> packed half2 words
__device__ __forceinline__ void split4h(float4 v, uint2& hi, uint2& lo) {
    __half h0 = __float2half(v.x), h1 = __float2half(v.y);
    __half h2 = __float2half(v.z), h3 = __float2half(v.w);
    __half l0 = __float2half(v.x - __half2float(h0));
    __half l1 = __float2half(v.y - __half2float(h1));
    __half l2 = __float2half(v.z - __half2float(h2));
    __half l3 = __float2half(v.w - __half2float(h3));
    hi.x = (uint32_t)__half_as_ushort(h0) | ((uint32_t)__half_as_ushort(h1) << 16);
    hi.y = (uint32_t)__half_as_ushort(h2) | ((uint32_t)__half_as_ushort(h3) << 16);
    lo.x = (uint32_t)__half_as_ushort(l0) | ((uint32_t)__half_as_ushort(l1) << 16);
    lo.y = (uint32_t)__half_as_ushort(l2) | ((uint32_t)__half_as_ushort(l3) << 16);
}

// weights -> hi/lo
__global__ void __launch_bounds__(256) convert_w_kernel(const float* __restrict__ Wq,
                                                        const float* __restrict__ Wk,
                                                        const float* __restrict__ Wv,
                                                        const float* __restrict__ Wo)
{
    int w = blockIdx.y;
    const float* src = (w == 0) ? Wq : (w == 1) ? Wk : (w == 2) ? Wv : Wo;
    int i = (blockIdx.x * 256 + threadIdx.x) * 4;
    float4 v = *(const float4*)(src + i);
    uint2 hi, lo; split4h(v, hi, lo);
    *(uint2*)(&g_w_h[w][i]) = hi;
    *(uint2*)(&g_w_l[w][i]) = lo;
}

// xp = [pm(4); x(2048); pad zeros to 2176] -> hi/lo
__global__ void __launch_bounds__(256) convert_xp_kernel(const float* __restrict__ pm,
                                                         const float* __restrict__ x)
{
    int i = (blockIdx.x * 256 + threadIdx.x) * 4;
    int row = i >> 10, col = i & 1023;
    float4 v = make_float4(0.f, 0.f, 0.f, 0.f);
    if (row < NP)          v = *(const float4*)(pm + row * D_MODEL + col);
    else if (row < T_TOT)  v = *(const float4*)(x + (size_t)(row - NP) * D_MODEL + col);
    uint2 hi, lo; split4h(v, hi, lo);
    *(uint2*)(&g_xp_h[i]) = hi;
    *(uint2*)(&g_xp_l[i]) = lo;
}

// ---------------- mma.sync GEMM: C[128,128]-tile = A @ B^T ----------------
// A,B given as fp16 hi/lo pairs; 3 mma passes (hh, hl, lh) into fp32 acc.
// SMEM per stage: Ah(16K) Al(16K) Bh(16K) Bl(16K) = 64KB, 2 stages = 128KB.
// Tiles: 128 rows x 64 halfs (128B rows), XOR-swizzled 16B chunks.
#define GEMM_SMEM (2 * 65536)

__device__ __forceinline__ void gemm128_body(const __half* __restrict__ Ah,
                                             const __half* __restrict__ Al,
                                             const __half* __restrict__ Bh,
                                             const __half* __restrict__ Bl,
                                             float* __restrict__ C, int Mrows)
{
    extern __shared__ __align__(1024) char sm[];
    uint32_t sbase = smem_u32(sm);
    int tid = threadIdx.x;
    int lane = tid & 31, wid = tid >> 5;
    int bm = blockIdx.y, bn = blockIdx.x;

    const __half* srcs[4] = {
        Ah + (size_t)bm * 128 * D_MODEL, Al + (size_t)bm * 128 * D_MODEL,
        Bh + (size_t)bn * 128 * D_MODEL, Bl + (size_t)bn * 128 * D_MODEL };

    // cp.async geometry: 4 mats * 1024 chunks of 16B; 4096 chunks / 256 thr = 16 per thread
    // chunk g: mat = g>>10, row = (g&1023)>>3, c = (g&1023)&7
    // issue one K-chunk (64 halfs = 128B per row) into stage s
    auto issue_chunk = [&](int kc, int s) {
        uint32_t stage = sbase + s * 65536;
#pragma unroll
        for (int it = 0; it < 16; it++) {
            int g = it * 256 + tid;
            int mat = g >> 10;
            int r = (g & 1023) >> 3;
            int c = g & 7;
            const __half* gp = srcs[mat] + (size_t)r * D_MODEL + kc * 64 + c * 8;
            uint32_t so = stage + mat * 16384 + r * 128 + ((c * 16) ^ ((r & 7) << 4));
            CP_ASYNC16(so, gp);
        }
    };

    // warp tiling: 4x2 warps, warp tile 32(M) x 64(N)
    int m_base = (wid & 3) * 32;
    int n_base = (wid >> 2) * 64;

    // ldmatrix lane geometry
    int arow0 = m_base + (lane & 15);            // + mi*16
    int ak2 = ((lane >> 4) * 8) * 2;             // k byte offset within frag
    int brow0 = n_base + (lane & 7) + ((lane >> 4) << 3);  // + p*16
    int bk2 = (((lane >> 3) & 1) * 8) * 2;

    uint32_t aoffs[2], asw[2], boffs[4], bsw[4];
#pragma unroll
    for (int mi = 0; mi < 2; mi++) {
        int r = arow0 + mi * 16;
        aoffs[mi] = r * 128; asw[mi] = (r & 7) << 4;
    }
#pragma unroll
    for (int p = 0; p < 4; p++) {
        int r = brow0 + p * 16;
        boffs[p] = r * 128; bsw[p] = (r & 7) << 4;
    }

    float acc[2][8][4];
#pragma unroll
    for (int mi = 0; mi < 2; mi++)
#pragma unroll
        for (int n = 0; n < 8; n++)
#pragma unroll
            for (int j = 0; j < 4; j++) acc[mi][n][j] = 0.f;

    issue_chunk(0, 0); CP_COMMIT();
    issue_chunk(1, 1); CP_COMMIT();

    for (int kc = 0; kc < 16; kc++) {
        CP_WAIT1();
        __syncthreads();
        uint32_t stage = sbase + (kc & 1) * 65536;
        uint32_t AH = stage, AL = stage + 16384, BH = stage + 32768, BL = stage + 49152;
#pragma unroll
        for (int ks = 0; ks < 4; ks++) {
            uint32_t kb2 = ks * 32;  // 16 halfs = 32B per kstep
            uint32_t ah[2][4], al[2][4];
#pragma unroll
            for (int mi = 0; mi < 2; mi++) {
                LDSM4(ah[mi][0], ah[mi][1], ah[mi][2], ah[mi][3],
                      AH + aoffs[mi] + ((kb2 + ak2) ^ asw[mi]));
                LDSM4(al[mi][0], al[mi][1], al[mi][2], al[mi][3],
                      AL + aoffs[mi] + ((kb2 + ak2) ^ asw[mi]));
            }
#pragma unroll
            for (int p = 0; p < 4; p++) {
                uint32_t bh[4], bl[4];
                LDSM4(bh[0], bh[1], bh[2], bh[3], BH + boffs[p] + ((kb2 + bk2) ^ bsw[p]));
                LDSM4(bl[0], bl[1], bl[2], bl[3], BL + boffs[p] + ((kb2 + bk2) ^ bsw[p]));
#pragma unroll
                for (int mi = 0; mi < 2; mi++) {
                    MMA16816(acc[mi][2 * p],     ah[mi][0], ah[mi][1], ah[mi][2], ah[mi][3], bh[0], bh[1]);
                    MMA16816(acc[mi][2 * p],     ah[mi][0], ah[mi][1], ah[mi][2], ah[mi][3], bl[0], bl[1]);
                    MMA16816(acc[mi][2 * p],     al[mi][0], al[mi][1], al[mi][2], al[mi][3], bh[0], bh[1]);
                    MMA16816(acc[mi][2 * p + 1], ah[mi][0], ah[mi][1], ah[mi][2], ah[mi][3], bh[2], bh[3]);
                    MMA16816(acc[mi][2 * p + 1], ah[mi][0], ah[mi][1], ah[mi][2], ah[mi][3], bl[2], bl[3]);
                    MMA16816(acc[mi][2 * p + 1], al[mi][0], al[mi][1], al[mi][2], al[mi][3], bh[2], bh[3]);
                }
            }
        }
        __syncthreads();
        int c2 = kc + 2;
        if (c2 < 16) issue_chunk(c2, kc & 1);
        CP_COMMIT();
    }

    // epilogue
    int crow = lane >> 2;
    int ccol = (lane & 3) * 2;
#pragma unroll
    for (int mi = 0; mi < 2; mi++) {
#pragma unroll
        for (int n = 0; n < 8; n++) {
            int row0 = bm * 128 + m_base + mi * 16 + crow;
            int col = bn * 128 + n_base + n * 8 + ccol;
            if (row0 < Mrows)
                *(float2*)(C + (size_t)row0 * D_MODEL + col) = make_float2(acc[mi][n][0], acc[mi][n][1]);
            int row1 = row0 + 8;
            if (row1 < Mrows)
                *(float2*)(C + (size_t)row1 * D_MODEL + col) = make_float2(acc[mi][n][2], acc[mi][n][3]);
        }
    }
}

__global__ void __launch_bounds__(256, 1) gemm_qkv_tc(void)
{
    int z = blockIdx.z;
    gemm128_body(g_xp_h, g_xp_l, g_w_h[z], g_w_l[z], g_QKV[z], T_TOT);
}
__global__ void __launch_bounds__(256, 1) gemm_out_tc(float* __restrict__ out)
{
    gemm128_body(g_at_h, g_at_l, g_w_h[3], g_w_l[3], out, L_SEQ);
}

// ---------------- fused depthwise causal conv(k=3) + bias + SiLU + (L2 norm for Q,K) ----
__global__ void __launch_bounds__(256) conv_silu_norm_kernel(const float* __restrict__ qw,
                                                             const float* __restrict__ qb,
                                                             const float* __restrict__ kw,
                                                             const float* __restrict__ kb,
                                                             const float* __restrict__ vw,
                                                             const float* __restrict__ vb)
{
    int m = blockIdx.y;
    int t = blockIdx.x;
    const float* w = (m == 0) ? qw : (m == 1) ? kw : vw;
    const float* b = (m == 0) ? qb : (m == 1) ? kb : vb;
    const float* X = g_QKV[m];
    float* Y = g_QKVc[m];
    int tid = threadIdx.x;

    float vals[4];
    float ss = 0.f;
#pragma unroll
    for (int i = 0; i < 4; i++) {
        int d = tid + i * 256;
        float x0 = (t >= 2) ? X[(size_t)(t - 2) * D_MODEL + d] : 0.f;
        float x1 = (t >= 1) ? X[(size_t)(t - 1) * D_MODEL + d] : 0.f;
        float x2 = X[(size_t)t * D_MODEL + d];
        float z = w[d * 3 + 0] * x0 + w[d * 3 + 1] * x1 + w[d * 3 + 2] * x2 + b[d];
        float y = z / (1.f + __expf(-z));
        vals[i] = y;
        ss += y * y;
    }
    __shared__ float red[8];
#pragma unroll
    for (int o = 16; o > 0; o >>= 1) ss += __shfl_xor_sync(0xffffffffu, ss, o);
    if ((tid & 31) == 0) red[tid >> 5] = ss;
    __syncthreads();
    if (tid < 32) {
        float v = (tid < 8) ? red[tid] : 0.f;
#pragma unroll
        for (int o = 4; o > 0; o >>= 1) v += __shfl_xor_sync(0xffffffffu, v, o);
        if (tid == 0) red[0] = v;
    }
    __syncthreads();
    float total = red[0];
    float inv = 1.f;
    if (m < 2) inv = 1.f / fmaxf(sqrtf(total), 1e-12f);
#pragma unroll
    for (int i = 0; i < 4; i++) {
        int d = tid + i * 256;
        Y[(size_t)t * D_MODEL + d] = vals[i] * inv;
    }
}

// ---------------- attention ----------------
#define KSLOTS 260

#define ATTN_PROCESS(SLOT)                                                        \
    do {                                                                          \
        int _s = (SLOT);                                                          \
        const float4* kr = (const float4*)(Ks + _s * HD);                         \
        float s0 = 0.f, s1 = 0.f, s2 = 0.f, s3 = 0.f;                             \
        _Pragma("unroll")                                                         \
        for (int i = 0; i < 16; i += 4) {                                         \
            float4 k0 = kr[i + 0], k1 = kr[i + 1], k2 = kr[i + 2], k3 = kr[i + 3];\
            s0 += qv[i+0].x*k0.x + qv[i+0].y*k0.y + qv[i+0].z*k0.z + qv[i+0].w*k0.w;\
            s1 += qv[i+1].x*k1.x + qv[i+1].y*k1.y + qv[i+1].z*k1.z + qv[i+1].w*k1.w;\
            s2 += qv[i+2].x*k2.x + qv[i+2].y*k2.y + qv[i+2].z*k2.z + qv[i+2].w*k2.w;\
            s3 += qv[i+3].x*k3.x + qv[i+3].y*k3.y + qv[i+3].z*k3.z + qv[i+3].w*k3.w;\
        }                                                                         \
        float p = __expf((s0 + s1 + s2 + s3) * 0.125f);                           \
        l += p;                                                                   \
        const float4* vr = (const float4*)(Vs + _s * HD);                         \
        _Pragma("unroll")                                                         \
        for (int i = 0; i < 16; i++) {                                            \
            float4 v4 = vr[i];                                                    \
            o[i].x += p * v4.x; o[i].y += p * v4.y;                               \
            o[i].z += p * v4.z; o[i].w += p * v4.w;                               \
        }                                                                         \
    } while (0)

__global__ void __launch_bounds__(128, 1) attn_kernel()
{
    extern __shared__ __align__(1024) char smc[];
    float* Ks = (float*)smc;
    float* Vs = (float*)smc + KSLOTS * HD;

    const float* Qg = g_QKVc[0];
    const float* Kg = g_QKVc[1];
    const float* Vg = g_QKVc[2];

    int h = blockIdx.x;
    int tile = blockIdx.y;
    int q0 = NP + tile * 128;
    int kmin = q0 - (WIN - 1);
    if (kmin < NP) kmin = NP;
    int kmaxq = q0 + 127;
    int total = 4 + (kmaxq - kmin + 1);
    int tid = threadIdx.x;
    int hoff = h * HD;

    for (int idx = tid; idx < total * 16; idx += 128) {
        int slot = idx >> 4, c = idx & 15;
        int key = (slot < 4) ? slot : (kmin + slot - 4);
        ((float4*)Ks)[slot * 16 + c] = *(const float4*)(Kg + (size_t)key * D_MODEL + hoff + c * 4);
        ((float4*)Vs)[slot * 16 + c] = *(const float4*)(Vg + (size_t)key * D_MODEL + hoff + c * 4);
    }
    __syncthreads();

    int q = q0 + tid;
    float4 qv[16];
#pragma unroll
    for (int i = 0; i < 16; i++)
        qv[i] = *(const float4*)(Qg + (size_t)q * D_MODEL + hoff + i * 4);

    float4 o[16];
#pragma unroll
    for (int i = 0; i < 16; i++) o[i] = make_float4(0.f, 0.f, 0.f, 0.f);
    float l = 0.f;

#pragma unroll
    for (int s = 0; s < 4; s++) ATTN_PROCESS(s);

    int ks = q - (WIN - 1);
    if (ks < NP) ks = NP;
    for (int k = ks; k <= q; k++) ATTN_PROCESS(4 + k - kmin);

    // write fp16 hi/lo split directly (consumed by the out-projection GEMM)
    float inv = 1.f / l;
    size_t rbase = (size_t)(q - NP) * D_MODEL + hoff;
#pragma unroll
    for (int i = 0; i < 16; i++) {
        float4 v = make_float4(o[i].x * inv, o[i].y * inv, o[i].z * inv, o[i].w * inv);
        uint2 hi, lo; split4h(v, hi, lo);
        *(uint2*)(&g_at_h[rbase + i * 4]) = hi;
        *(uint2*)(&g_at_l[rbase + i * 4]) = lo;
    }
}

// ---------------- launch ----------------
extern "C" void kernel_launch(void* const* d_in, const int* in_sizes, int n_in,
                              void* d_out, int out_size)
{
    (void)in_sizes; (void)n_in; (void)out_size;
    const float* x  = (const float*)d_in[0];
    const float* pm = (const float*)d_in[1];
    const float* Wq = (const float*)d_in[2];
    const float* Wk = (const float*)d_in[3];
    const float* Wv = (const float*)d_in[4];
    const float* Wo = (const float*)d_in[5];
    const float* qw = (const float*)d_in[6];
    const float* qb = (const float*)d_in[7];
    const float* kw = (const float*)d_in[8];
    const float* kb = (const float*)d_in[9];
    const float* vw = (const float*)d_in[10];
    const float* vb = (const float*)d_in[11];
    float* out = (float*)d_out;

    const int attn_smem = 2 * KSLOTS * HD * (int)sizeof(float);
    cudaFuncSetAttribute(attn_kernel, cudaFuncAttributeMaxDynamicSharedMemorySize, attn_smem);
    cudaFuncSetAttribute(gemm_qkv_tc, cudaFuncAttributeMaxDynamicSharedMemorySize, GEMM_SMEM);
    cudaFuncSetAttribute(gemm_out_tc, cudaFuncAttributeMaxDynamicSharedMemorySize, GEMM_SMEM);

    convert_w_kernel<<<dim3(D_MODEL * D_MODEL / 1024, 4), 256>>>(Wq, Wk, Wv, Wo);
    convert_xp_kernel<<<MPAD * D_MODEL / 1024, 256>>>(pm, x);

    gemm_qkv_tc<<<dim3(8, 17, 3), 256, GEMM_SMEM>>>();

    conv_silu_norm_kernel<<<dim3(T_TOT, 3), 256>>>(qw, qb, kw, kb, vw, vb);

    attn_kernel<<<dim3(NHEADS, L_SEQ / 128), 128, attn_smem>>>();

    gemm_out_tc<<<dim3(8, 16, 1), 256, GEMM_SMEM>>>(out);
}

// round 5
// speedup vs baseline: 3.0353x; 3.0353x over previous
#include <cuda_runtime.h>
#include <cuda_fp16.h>
#include <math.h>
#include <stdint.h>

#define D_MODEL 1024
#define T_TOT   2052
#define MPAD    2176   // 17*128
#define L_SEQ   2048
#define NP      4
#define NHEADS  16
#define HD      64
#define WIN     128

// ---------------- scratch (device globals: allocation-free) ----------------
__device__ float g_QKV[3][T_TOT * D_MODEL];   // pre-conv Q,K,V (fp32)
__device__ float g_QKVc[3][T_TOT * D_MODEL];  // post conv+silu(+norm)
__device__ __half g_xp_h[MPAD * D_MODEL];
__device__ __half g_xp_l[MPAD * D_MODEL];
__device__ __half g_w_h[4][D_MODEL * D_MODEL];
__device__ __half g_w_l[4][D_MODEL * D_MODEL];
__device__ __half g_at_h[L_SEQ * D_MODEL];
__device__ __half g_at_l[L_SEQ * D_MODEL];

// ---------------- helpers ----------------
__device__ __forceinline__ uint32_t smem_u32(const void* p) {
    uint32_t a;
    asm("{ .reg .u64 t; cvta.to.shared.u64 t, %1; cvt.u32.u64 %0, t; }" : "=r"(a) : "l"(p));
    return a;
}

#define LDSM4(R0, R1, R2, R3, ADDR) \
    asm volatile("ldmatrix.sync.aligned.m8n8.x4.shared.b16 {%0,%1,%2,%3}, [%4];" \
                 : "=r"(R0), "=r"(R1), "=r"(R2), "=r"(R3) : "r"(ADDR))

#define MMA16816(D, A0, A1, A2, A3, B0, B1) \
    asm volatile("mma.sync.aligned.m16n8k16.row.col.f32.f16.f16.f32 " \
                 "{%0,%1,%2,%3}, {%4,%5,%6,%7}, {%8,%9}, {%0,%1,%2,%3};" \
                 : "+f"((D)[0]), "+f"((D)[1]), "+f"((D)[2]), "+f"((D)[3]) \
                 : "r"(A0), "r"(A1), "r"(A2), "r"(A3), "r"(B0), "r"(B1))

#define CP_ASYNC16(S, G) \
    asm volatile("cp.async.cg.shared.global [%0], [%1], 16;" :: "r"(S), "l"(G))
#define CP_COMMIT()  asm volatile("cp.async.commit_group;" ::: "memory")
#define CP_WAIT2()   asm volatile("cp.async.wait_group 2;" ::: "memory")

// fp16 hi/lo split of a float4 -> packed half2 words
__device__ __forceinline__ void split4h(float4 v, uint2& hi, uint2& lo) {
    __half h0 = __float2half(v.x), h1 = __float2half(v.y);
    __half h2 = __float2half(v.z), h3 = __float2half(v.w);
    __half l0 = __float2half(v.x - __half2float(h0));
    __half l1 = __float2half(v.y - __half2float(h1));
    __half l2 = __float2half(v.z - __half2float(h2));
    __half l3 = __float2half(v.w - __half2float(h3));
    hi.x = (uint32_t)__half_as_ushort(h0) | ((uint32_t)__half_as_ushort(h1) << 16);
    hi.y = (uint32_t)__half_as_ushort(h2) | ((uint32_t)__half_as_ushort(h3) << 16);
    lo.x = (uint32_t)__half_as_ushort(l0) | ((uint32_t)__half_as_ushort(l1) << 16);
    lo.y = (uint32_t)__half_as_ushort(l2) | ((uint32_t)__half_as_ushort(l3) << 16);
}

// weights -> hi/lo
__global__ void __launch_bounds__(256) convert_w_kernel(const float* __restrict__ Wq,
                                                        const float* __restrict__ Wk,
                                                        const float* __restrict__ Wv,
                                                        const float* __restrict__ Wo)
{
    int w = blockIdx.y;
    const float* src = (w == 0) ? Wq : (w == 1) ? Wk : (w == 2) ? Wv : Wo;
    int i = (blockIdx.x * 256 + threadIdx.x) * 4;
    float4 v = *(const float4*)(src + i);
    uint2 hi, lo; split4h(v, hi, lo);
    *(uint2*)(&g_w_h[w][i]) = hi;
    *(uint2*)(&g_w_l[w][i]) = lo;
}

// xp = [pm(4); x(2048); pad zeros to 2176] -> hi/lo
__global__ void __launch_bounds__(256) convert_xp_kernel(const float* __restrict__ pm,
                                                         const float* __restrict__ x)
{
    int i = (blockIdx.x * 256 + threadIdx.x) * 4;
    int row = i >> 10, col = i & 1023;
    float4 v = make_float4(0.f, 0.f, 0.f, 0.f);
    if (row < NP)          v = *(const float4*)(pm + row * D_MODEL + col);
    else if (row < T_TOT)  v = *(const float4*)(x + (size_t)(row - NP) * D_MODEL + col);
    uint2 hi, lo; split4h(v, hi, lo);
    *(uint2*)(&g_xp_h[i]) = hi;
    *(uint2*)(&g_xp_l[i]) = lo;
}

// ---------------- mma.sync GEMM: C[128,128]-tile = A @ B^T ----------------
// A,B fp16 hi/lo; 3 mma passes (hh, hl, lh) into fp32 acc.
// 3-stage cp.async pipeline: stage = Ah(16K) Al(16K) Bh(16K) Bl(16K) = 64KB.
#define GEMM_SMEM (3 * 65536)

__device__ __forceinline__ void gemm128_body(const __half* __restrict__ Ah,
                                             const __half* __restrict__ Al,
                                             const __half* __restrict__ Bh,
                                             const __half* __restrict__ Bl,
                                             float* __restrict__ C, int Mrows)
{
    extern __shared__ __align__(1024) char sm[];
    uint32_t sbase = smem_u32(sm);
    int tid = threadIdx.x;
    int lane = tid & 31, wid = tid >> 5;
    int bm = blockIdx.y, bn = blockIdx.x;

    const __half* srcs[4] = {
        Ah + (size_t)bm * 128 * D_MODEL, Al + (size_t)bm * 128 * D_MODEL,
        Bh + (size_t)bn * 128 * D_MODEL, Bl + (size_t)bn * 128 * D_MODEL };

    // one K-chunk (64 halfs = 128B per row) into stage s (= chunk % 3)
    auto issue_chunk = [&](int kc, int s) {
        uint32_t stage = sbase + s * 65536;
#pragma unroll
        for (int it = 0; it < 16; it++) {
            int g = it * 256 + tid;
            int mat = g >> 10;
            int r = (g & 1023) >> 3;
            int c = g & 7;
            const __half* gp = srcs[mat] + (size_t)r * D_MODEL + kc * 64 + c * 8;
            uint32_t so = stage + mat * 16384 + r * 128 + ((c * 16) ^ ((r & 7) << 4));
            CP_ASYNC16(so, gp);
        }
    };

    // warp tiling: 4x2 warps, warp tile 32(M) x 64(N)
    int m_base = (wid & 3) * 32;
    int n_base = (wid >> 2) * 64;

    int arow0 = m_base + (lane & 15);
    int ak2 = ((lane >> 4) * 8) * 2;
    int brow0 = n_base + (lane & 7) + ((lane >> 4) << 3);
    int bk2 = (((lane >> 3) & 1) * 8) * 2;

    uint32_t aoffs[2], asw[2], boffs[4], bsw[4];
#pragma unroll
    for (int mi = 0; mi < 2; mi++) {
        int r = arow0 + mi * 16;
        aoffs[mi] = r * 128; asw[mi] = (r & 7) << 4;
    }
#pragma unroll
    for (int p = 0; p < 4; p++) {
        int r = brow0 + p * 16;
        boffs[p] = r * 128; bsw[p] = (r & 7) << 4;
    }

    float acc[2][8][4];
#pragma unroll
    for (int mi = 0; mi < 2; mi++)
#pragma unroll
        for (int n = 0; n < 8; n++)
#pragma unroll
            for (int j = 0; j < 4; j++) acc[mi][n][j] = 0.f;

    issue_chunk(0, 0); CP_COMMIT();
    issue_chunk(1, 1); CP_COMMIT();
    issue_chunk(2, 2); CP_COMMIT();

    for (int kc = 0; kc < 16; kc++) {
        CP_WAIT2();
        __syncthreads();
        uint32_t stage = sbase + (kc % 3) * 65536;
        uint32_t AH = stage, AL = stage + 16384, BH = stage + 32768, BL = stage + 49152;
#pragma unroll
        for (int ks = 0; ks < 4; ks++) {
            uint32_t kb2 = ks * 32;
            uint32_t ah[2][4], al[2][4];
#pragma unroll
            for (int mi = 0; mi < 2; mi++) {
                LDSM4(ah[mi][0], ah[mi][1], ah[mi][2], ah[mi][3],
                      AH + aoffs[mi] + ((kb2 + ak2) ^ asw[mi]));
                LDSM4(al[mi][0], al[mi][1], al[mi][2], al[mi][3],
                      AL + aoffs[mi] + ((kb2 + ak2) ^ asw[mi]));
            }
#pragma unroll
            for (int p = 0; p < 4; p++) {
                uint32_t bh[4], bl[4];
                LDSM4(bh[0], bh[1], bh[2], bh[3], BH + boffs[p] + ((kb2 + bk2) ^ bsw[p]));
                LDSM4(bl[0], bl[1], bl[2], bl[3], BL + boffs[p] + ((kb2 + bk2) ^ bsw[p]));
#pragma unroll
                for (int mi = 0; mi < 2; mi++) {
                    MMA16816(acc[mi][2 * p],     ah[mi][0], ah[mi][1], ah[mi][2], ah[mi][3], bh[0], bh[1]);
                    MMA16816(acc[mi][2 * p],     ah[mi][0], ah[mi][1], ah[mi][2], ah[mi][3], bl[0], bl[1]);
                    MMA16816(acc[mi][2 * p],     al[mi][0], al[mi][1], al[mi][2], al[mi][3], bh[0], bh[1]);
                    MMA16816(acc[mi][2 * p + 1], ah[mi][0], ah[mi][1], ah[mi][2], ah[mi][3], bh[2], bh[3]);
                    MMA16816(acc[mi][2 * p + 1], ah[mi][0], ah[mi][1], ah[mi][2], ah[mi][3], bl[2], bl[3]);
                    MMA16816(acc[mi][2 * p + 1], al[mi][0], al[mi][1], al[mi][2], al[mi][3], bh[2], bh[3]);
                }
            }
        }
        __syncthreads();
        int c3 = kc + 3;
        if (c3 < 16) issue_chunk(c3, c3 % 3);
        CP_COMMIT();
    }

    // epilogue
    int crow = lane >> 2;
    int ccol = (lane & 3) * 2;
#pragma unroll
    for (int mi = 0; mi < 2; mi++) {
#pragma unroll
        for (int n = 0; n < 8; n++) {
            int row0 = bm * 128 + m_base + mi * 16 + crow;
            int col = bn * 128 + n_base + n * 8 + ccol;
            if (row0 < Mrows)
                *(float2*)(C + (size_t)row0 * D_MODEL + col) = make_float2(acc[mi][n][0], acc[mi][n][1]);
            int row1 = row0 + 8;
            if (row1 < Mrows)
                *(float2*)(C + (size_t)row1 * D_MODEL + col) = make_float2(acc[mi][n][2], acc[mi][n][3]);
        }
    }
}

__global__ void __launch_bounds__(256, 1) gemm_qkv_tc(void)
{
    int z = blockIdx.z;
    gemm128_body(g_xp_h, g_xp_l, g_w_h[z], g_w_l[z], g_QKV[z], T_TOT);
}
__global__ void __launch_bounds__(256, 1) gemm_out_tc(float* __restrict__ out)
{
    gemm128_body(g_at_h, g_at_l, g_w_h[3], g_w_l[3], out, L_SEQ);
}

// ---------------- fused depthwise causal conv(k=3) + bias + SiLU + (L2 norm for Q,K) ----
__global__ void __launch_bounds__(256) conv_silu_norm_kernel(const float* __restrict__ qw,
                                                             const float* __restrict__ qb,
                                                             const float* __restrict__ kw,
                                                             const float* __restrict__ kb,
                                                             const float* __restrict__ vw,
                                                             const float* __restrict__ vb)
{
    int m = blockIdx.y;
    int t = blockIdx.x;
    const float* w = (m == 0) ? qw : (m == 1) ? kw : vw;
    const float* b = (m == 0) ? qb : (m == 1) ? kb : vb;
    const float* X = g_QKV[m];
    float* Y = g_QKVc[m];
    int tid = threadIdx.x;

    float vals[4];
    float ss = 0.f;
#pragma unroll
    for (int i = 0; i < 4; i++) {
        int d = tid + i * 256;
        float x0 = (t >= 2) ? X[(size_t)(t - 2) * D_MODEL + d] : 0.f;
        float x1 = (t >= 1) ? X[(size_t)(t - 1) * D_MODEL + d] : 0.f;
        float x2 = X[(size_t)t * D_MODEL + d];
        float z = w[d * 3 + 0] * x0 + w[d * 3 + 1] * x1 + w[d * 3 + 2] * x2 + b[d];
        float y = z / (1.f + __expf(-z));
        vals[i] = y;
        ss += y * y;
    }
    __shared__ float red[8];
#pragma unroll
    for (int o = 16; o > 0; o >>= 1) ss += __shfl_xor_sync(0xffffffffu, ss, o);
    if ((tid & 31) == 0) red[tid >> 5] = ss;
    __syncthreads();
    if (tid < 32) {
        float v = (tid < 8) ? red[tid] : 0.f;
#pragma unroll
        for (int o = 4; o > 0; o >>= 1) v += __shfl_xor_sync(0xffffffffu, v, o);
        if (tid == 0) red[0] = v;
    }
    __syncthreads();
    float total = red[0];
    float inv = 1.f;
    if (m < 2) inv = 1.f / fmaxf(sqrtf(total), 1e-12f);
#pragma unroll
    for (int i = 0; i < 4; i++) {
        int d = tid + i * 256;
        Y[(size_t)t * D_MODEL + d] = vals[i] * inv;
    }
}

// ---------------- attention (warp-synchronized keys: broadcast smem reads) ----
// Block: 256 threads = 8 warps; warp w owns queries q0+w*32+lane (256 q/block).
// All lanes of a warp process the SAME key k each trip -> smem broadcast.
#define QTILE  256
#define KSLOTS 388   // 4 persistent + up to 383 window keys + pad
#define ATTN_SMEM (2 * KSLOTS * HD * 4)

__global__ void __launch_bounds__(256, 1) attn_kernel()
{
    extern __shared__ __align__(1024) char smc[];
    float* Ks = (float*)smc;
    float* Vs = (float*)smc + KSLOTS * HD;

    const float* Qg = g_QKVc[0];
    const float* Kg = g_QKVc[1];
    const float* Vg = g_QKVc[2];

    int h = blockIdx.x;
    int tile = blockIdx.y;
    int q0 = NP + tile * QTILE;
    int kmin = q0 - (WIN - 1);
    if (kmin < NP) kmin = NP;
    int kmax = q0 + QTILE - 1;
    int total = 4 + (kmax - kmin + 1);
    int tid = threadIdx.x;
    int lane = tid & 31, w = tid >> 5;
    int hoff = h * HD;

    for (int idx = tid; idx < total * 16; idx += 256) {
        int slot = idx >> 4, c = idx & 15;
        int key = (slot < 4) ? slot : (kmin + slot - 4);
        ((float4*)Ks)[slot * 16 + c] = *(const float4*)(Kg + (size_t)key * D_MODEL + hoff + c * 4);
        ((float4*)Vs)[slot * 16 + c] = *(const float4*)(Vg + (size_t)key * D_MODEL + hoff + c * 4);
    }
    __syncthreads();

    int q = q0 + w * 32 + lane;
    float4 qv[16];
#pragma unroll
    for (int i = 0; i < 16; i++)
        qv[i] = *(const float4*)(Qg + (size_t)q * D_MODEL + hoff + i * 4);

    float4 o[16];
#pragma unroll
    for (int i = 0; i < 16; i++) o[i] = make_float4(0.f, 0.f, 0.f, 0.f);
    float l = 0.f;

    // persistent keys: slots 0..3, always allowed
#pragma unroll
    for (int s = 0; s < 4; s++) {
        const float4* kr = (const float4*)(Ks + s * HD);
        float sc = 0.f;
#pragma unroll
        for (int i = 0; i < 16; i++) {
            float4 kk = kr[i];
            sc += qv[i].x * kk.x + qv[i].y * kk.y + qv[i].z * kk.z + qv[i].w * kk.w;
        }
        float p = __expf(sc * 0.125f);
        l += p;
        const float4* vr = (const float4*)(Vs + s * HD);
#pragma unroll
        for (int i = 0; i < 16; i++) {
            float4 v4 = vr[i];
            o[i].x += p * v4.x; o[i].y += p * v4.y;
            o[i].z += p * v4.z; o[i].w += p * v4.w;
        }
    }

    // window keys, warp-synchronized over absolute key index
    int q0w = q0 + w * 32;
    int kstart = q0w - (WIN - 1);
    if (kstart < NP) kstart = NP;
    int kend = q0w + 31;
    for (int k = kstart; k <= kend; k++) {
        int slot = 4 + k - kmin;
        const float4* kr = (const float4*)(Ks + slot * HD);
        float sc = 0.f;
#pragma unroll
        for (int i = 0; i < 16; i++) {
            float4 kk = kr[i];
            sc += qv[i].x * kk.x + qv[i].y * kk.y + qv[i].z * kk.z + qv[i].w * kk.w;
        }
        bool act = (k <= q) && (k >= q - (WIN - 1));
        float p = act ? __expf(sc * 0.125f) : 0.f;
        l += p;
        const float4* vr = (const float4*)(Vs + slot * HD);
#pragma unroll
        for (int i = 0; i < 16; i++) {
            float4 v4 = vr[i];
            o[i].x += p * v4.x; o[i].y += p * v4.y;
            o[i].z += p * v4.z; o[i].w += p * v4.w;
        }
    }

    // write fp16 hi/lo split directly (consumed by the out-projection GEMM)
    float inv = 1.f / l;
    size_t rbase = (size_t)(q - NP) * D_MODEL + hoff;
#pragma unroll
    for (int i = 0; i < 16; i++) {
        float4 v = make_float4(o[i].x * inv, o[i].y * inv, o[i].z * inv, o[i].w * inv);
        uint2 hi, lo; split4h(v, hi, lo);
        *(uint2*)(&g_at_h[rbase + i * 4]) = hi;
        *(uint2*)(&g_at_l[rbase + i * 4]) = lo;
    }
}

// ---------------- launch ----------------
extern "C" void kernel_launch(void* const* d_in, const int* in_sizes, int n_in,
                              void* d_out, int out_size)
{
    (void)in_sizes; (void)n_in; (void)out_size;
    const float* x  = (const float*)d_in[0];
    const float* pm = (const float*)d_in[1];
    const float* Wq = (const float*)d_in[2];
    const float* Wk = (const float*)d_in[3];
    const float* Wv = (const float*)d_in[4];
    const float* Wo = (const float*)d_in[5];
    const float* qw = (const float*)d_in[6];
    const float* qb = (const float*)d_in[7];
    const float* kw = (const float*)d_in[8];
    const float* kb = (const float*)d_in[9];
    const float* vw = (const float*)d_in[10];
    const float* vb = (const float*)d_in[11];
    float* out = (float*)d_out;

    cudaFuncSetAttribute(attn_kernel, cudaFuncAttributeMaxDynamicSharedMemorySize, ATTN_SMEM);
    cudaFuncSetAttribute(gemm_qkv_tc, cudaFuncAttributeMaxDynamicSharedMemorySize, GEMM_SMEM);
    cudaFuncSetAttribute(gemm_out_tc, cudaFuncAttributeMaxDynamicSharedMemorySize, GEMM_SMEM);

    convert_w_kernel<<<dim3(D_MODEL * D_MODEL / 1024, 4), 256>>>(Wq, Wk, Wv, Wo);
    convert_xp_kernel<<<MPAD * D_MODEL / 1024, 256>>>(pm, x);

    gemm_qkv_tc<<<dim3(8, 17, 3), 256, GEMM_SMEM>>>();

    conv_silu_norm_kernel<<<dim3(T_TOT, 3), 256>>>(qw, qb, kw, kb, vw, vb);

    attn_kernel<<<dim3(NHEADS, L_SEQ / QTILE), 256, ATTN_SMEM>>>();

    gemm_out_tc<<<dim3(8, 16, 1), 256, GEMM_SMEM>>>(out);
}

// round 7
// speedup vs baseline: 3.5743x; 1.1776x over previous
#include <cuda_runtime.h>
#include <cuda_fp16.h>
#include <math.h>
#include <stdint.h>

#define D_MODEL 1024
#define T_TOT   2052
#define MPAD    2176   // 17*128
#define L_SEQ   2048
#define NP      4
#define NHEADS  16
#define HD      64
#define WIN     128

// ---------------- scratch (device globals: allocation-free) ----------------
__device__ float g_QKV[3][T_TOT * D_MODEL];   // pre-conv Q,K,V (fp32, GEMM out)
__device__ __half g_Qh[T_TOT * D_MODEL];      // post conv+silu+norm, fp16
__device__ __half g_Kh[T_TOT * D_MODEL];
__device__ __half g_Vh[T_TOT * D_MODEL];      // V hi
__device__ __half g_Vl[T_TOT * D_MODEL];      // V lo residual
__device__ __half g_xp_h[MPAD * D_MODEL];
__device__ __half g_xp_l[MPAD * D_MODEL];
__device__ __half g_w_h[4][D_MODEL * D_MODEL];
__device__ __half g_w_l[4][D_MODEL * D_MODEL];
__device__ __half g_at_h[L_SEQ * D_MODEL];
__device__ __half g_at_l[L_SEQ * D_MODEL];

// ---------------- helpers ----------------
__device__ __forceinline__ uint32_t smem_u32(const void* p) {
    uint32_t a;
    asm("{ .reg .u64 t; cvta.to.shared.u64 t, %1; cvt.u32.u64 %0, t; }" : "=r"(a) : "l"(p));
    return a;
}

#define LDSM4(R0, R1, R2, R3, ADDR) \
    asm volatile("ldmatrix.sync.aligned.m8n8.x4.shared.b16 {%0,%1,%2,%3}, [%4];" \
                 : "=r"(R0), "=r"(R1), "=r"(R2), "=r"(R3) : "r"(ADDR))

#define LDSM2T(R0, R1, ADDR) \
    asm volatile("ldmatrix.sync.aligned.m8n8.x2.trans.shared.b16 {%0,%1}, [%2];" \
                 : "=r"(R0), "=r"(R1) : "r"(ADDR))

#define MMA16816(D, A0, A1, A2, A3, B0, B1) \
    asm volatile("mma.sync.aligned.m16n8k16.row.col.f32.f16.f16.f32 " \
                 "{%0,%1,%2,%3}, {%4,%5,%6,%7}, {%8,%9}, {%0,%1,%2,%3};" \
                 : "+f"((D)[0]), "+f"((D)[1]), "+f"((D)[2]), "+f"((D)[3]) \
                 : "r"(A0), "r"(A1), "r"(A2), "r"(A3), "r"(B0), "r"(B1))

#define CP_ASYNC16(S, G) \
    asm volatile("cp.async.cg.shared.global [%0], [%1], 16;" :: "r"(S), "l"(G))
#define CP_COMMIT()  asm volatile("cp.async.commit_group;" ::: "memory")
#define CP_WAIT2()   asm volatile("cp.async.wait_group 2;" ::: "memory")

// fp16 hi/lo split of a float4 -> packed half2 words
__device__ __forceinline__ void split4h(float4 v, uint2& hi, uint2& lo) {
    __half h0 = __float2half(v.x), h1 = __float2half(v.y);
    __half h2 = __float2half(v.z), h3 = __float2half(v.w);
    __half l0 = __float2half(v.x - __half2float(h0));
    __half l1 = __float2half(v.y - __half2float(h1));
    __half l2 = __float2half(v.z - __half2float(h2));
    __half l3 = __float2half(v.w - __half2float(h3));
    hi.x = (uint32_t)__half_as_ushort(h0) | ((uint32_t)__half_as_ushort(h1) << 16);
    hi.y = (uint32_t)__half_as_ushort(h2) | ((uint32_t)__half_as_ushort(h3) << 16);
    lo.x = (uint32_t)__half_as_ushort(l0) | ((uint32_t)__half_as_ushort(l1) << 16);
    lo.y = (uint32_t)__half_as_ushort(l2) | ((uint32_t)__half_as_ushort(l3) << 16);
}
__device__ __forceinline__ uint32_t pack2h(float a, float b) {
    __half2 h = __floats2half2_rn(a, b);
    return *(uint32_t*)&h;
}

// weights -> hi/lo
__global__ void __launch_bounds__(256) convert_w_kernel(const float* __restrict__ Wq,
                                                        const float* __restrict__ Wk,
                                                        const float* __restrict__ Wv,
                                                        const float* __restrict__ Wo)
{
    int w = blockIdx.y;
    const float* src = (w == 0) ? Wq : (w == 1) ? Wk : (w == 2) ? Wv : Wo;
    int i = (blockIdx.x * 256 + threadIdx.x) * 4;
    float4 v = *(const float4*)(src + i);
    uint2 hi, lo; split4h(v, hi, lo);
    *(uint2*)(&g_w_h[w][i]) = hi;
    *(uint2*)(&g_w_l[w][i]) = lo;
}

// xp = [pm(4); x(2048); pad zeros to 2176] -> hi/lo
__global__ void __launch_bounds__(256) convert_xp_kernel(const float* __restrict__ pm,
                                                         const float* __restrict__ x)
{
    int i = (blockIdx.x * 256 + threadIdx.x) * 4;
    int row = i >> 10, col = i & 1023;
    float4 v = make_float4(0.f, 0.f, 0.f, 0.f);
    if (row < NP)          v = *(const float4*)(pm + row * D_MODEL + col);
    else if (row < T_TOT)  v = *(const float4*)(x + (size_t)(row - NP) * D_MODEL + col);
    uint2 hi, lo; split4h(v, hi, lo);
    *(uint2*)(&g_xp_h[i]) = hi;
    *(uint2*)(&g_xp_l[i]) = lo;
}

// ---------------- mma.sync GEMM: C[128,128]-tile = A @ B^T ----------------
#define GEMM_SMEM (3 * 65536)

__device__ __forceinline__ void gemm128_body(const __half* __restrict__ Ah,
                                             const __half* __restrict__ Al,
                                             const __half* __restrict__ Bh,
                                             const __half* __restrict__ Bl,
                                             float* __restrict__ C, int Mrows)
{
    extern __shared__ __align__(1024) char sm[];
    uint32_t sbase = smem_u32(sm);
    int tid = threadIdx.x;
    int lane = tid & 31, wid = tid >> 5;
    int bm = blockIdx.y, bn = blockIdx.x;

    const __half* srcs[4] = {
        Ah + (size_t)bm * 128 * D_MODEL, Al + (size_t)bm * 128 * D_MODEL,
        Bh + (size_t)bn * 128 * D_MODEL, Bl + (size_t)bn * 128 * D_MODEL };

    auto issue_chunk = [&](int kc, int s) {
        uint32_t stage = sbase + s * 65536;
#pragma unroll
        for (int it = 0; it < 16; it++) {
            int g = it * 256 + tid;
            int mat = g >> 10;
            int r = (g & 1023) >> 3;
            int c = g & 7;
            const __half* gp = srcs[mat] + (size_t)r * D_MODEL + kc * 64 + c * 8;
            uint32_t so = stage + mat * 16384 + r * 128 + ((c * 16) ^ ((r & 7) << 4));
            CP_ASYNC16(so, gp);
        }
    };

    int m_base = (wid & 3) * 32;
    int n_base = (wid >> 2) * 64;

    int arow0 = m_base + (lane & 15);
    int ak2 = ((lane >> 4) * 8) * 2;
    int brow0 = n_base + (lane & 7) + ((lane >> 4) << 3);
    int bk2 = (((lane >> 3) & 1) * 8) * 2;

    uint32_t aoffs[2], asw[2], boffs[4], bsw[4];
#pragma unroll
    for (int mi = 0; mi < 2; mi++) {
        int r = arow0 + mi * 16;
        aoffs[mi] = r * 128; asw[mi] = (r & 7) << 4;
    }
#pragma unroll
    for (int p = 0; p < 4; p++) {
        int r = brow0 + p * 16;
        boffs[p] = r * 128; bsw[p] = (r & 7) << 4;
    }

    float acc[2][8][4];
#pragma unroll
    for (int mi = 0; mi < 2; mi++)
#pragma unroll
        for (int n = 0; n < 8; n++)
#pragma unroll
            for (int j = 0; j < 4; j++) acc[mi][n][j] = 0.f;

    issue_chunk(0, 0); CP_COMMIT();
    issue_chunk(1, 1); CP_COMMIT();
    issue_chunk(2, 2); CP_COMMIT();

    for (int kc = 0; kc < 16; kc++) {
        CP_WAIT2();
        __syncthreads();
        uint32_t stage = sbase + (kc % 3) * 65536;
        uint32_t AH = stage, AL = stage + 16384, BH = stage + 32768, BL = stage + 49152;
#pragma unroll
        for (int ks = 0; ks < 4; ks++) {
            uint32_t kb2 = ks * 32;
            uint32_t ah[2][4], al[2][4];
#pragma unroll
            for (int mi = 0; mi < 2; mi++) {
                LDSM4(ah[mi][0], ah[mi][1], ah[mi][2], ah[mi][3],
                      AH + aoffs[mi] + ((kb2 + ak2) ^ asw[mi]));
                LDSM4(al[mi][0], al[mi][1], al[mi][2], al[mi][3],
                      AL + aoffs[mi] + ((kb2 + ak2) ^ asw[mi]));
            }
#pragma unroll
            for (int p = 0; p < 4; p++) {
                uint32_t bh[4], bl[4];
                LDSM4(bh[0], bh[1], bh[2], bh[3], BH + boffs[p] + ((kb2 + bk2) ^ bsw[p]));
                LDSM4(bl[0], bl[1], bl[2], bl[3], BL + boffs[p] + ((kb2 + bk2) ^ bsw[p]));
#pragma unroll
                for (int mi = 0; mi < 2; mi++) {
                    MMA16816(acc[mi][2 * p],     ah[mi][0], ah[mi][1], ah[mi][2], ah[mi][3], bh[0], bh[1]);
                    MMA16816(acc[mi][2 * p],     ah[mi][0], ah[mi][1], ah[mi][2], ah[mi][3], bl[0], bl[1]);
                    MMA16816(acc[mi][2 * p],     al[mi][0], al[mi][1], al[mi][2], al[mi][3], bh[0], bh[1]);
                    MMA16816(acc[mi][2 * p + 1], ah[mi][0], ah[mi][1], ah[mi][2], ah[mi][3], bh[2], bh[3]);
                    MMA16816(acc[mi][2 * p + 1], ah[mi][0], ah[mi][1], ah[mi][2], ah[mi][3], bl[2], bl[3]);
                    MMA16816(acc[mi][2 * p + 1], al[mi][0], al[mi][1], al[mi][2], al[mi][3], bh[2], bh[3]);
                }
            }
        }
        __syncthreads();
        int c3 = kc + 3;
        if (c3 < 16) issue_chunk(c3, c3 % 3);
        CP_COMMIT();
    }

    int crow = lane >> 2;
    int ccol = (lane & 3) * 2;
#pragma unroll
    for (int mi = 0; mi < 2; mi++) {
#pragma unroll
        for (int n = 0; n < 8; n++) {
            int row0 = bm * 128 + m_base + mi * 16 + crow;
            int col = bn * 128 + n_base + n * 8 + ccol;
            if (row0 < Mrows)
                *(float2*)(C + (size_t)row0 * D_MODEL + col) = make_float2(acc[mi][n][0], acc[mi][n][1]);
            int row1 = row0 + 8;
            if (row1 < Mrows)
                *(float2*)(C + (size_t)row1 * D_MODEL + col) = make_float2(acc[mi][n][2], acc[mi][n][3]);
        }
    }
}

__global__ void __launch_bounds__(256, 1) gemm_qkv_tc(void)
{
    int z = blockIdx.z;
    gemm128_body(g_xp_h, g_xp_l, g_w_h[z], g_w_l[z], g_QKV[z], T_TOT);
}
__global__ void __launch_bounds__(256, 1) gemm_out_tc(float* __restrict__ out)
{
    gemm128_body(g_at_h, g_at_l, g_w_h[3], g_w_l[3], out, L_SEQ);
}

// ---------------- fused conv(k=3) + bias + SiLU + (L2 norm) -> fp16 outputs ----
__global__ void __launch_bounds__(256) conv_silu_norm_kernel(const float* __restrict__ qw,
                                                             const float* __restrict__ qb,
                                                             const float* __restrict__ kw,
                                                             const float* __restrict__ kb,
                                                             const float* __restrict__ vw,
                                                             const float* __restrict__ vb)
{
    int m = blockIdx.y;
    int t = blockIdx.x;
    const float* w = (m == 0) ? qw : (m == 1) ? kw : vw;
    const float* b = (m == 0) ? qb : (m == 1) ? kb : vb;
    const float* X = g_QKV[m];
    int tid = threadIdx.x;

    float vals[4];
    float ss = 0.f;
#pragma unroll
    for (int i = 0; i < 4; i++) {
        int d = tid + i * 256;
        float x0 = (t >= 2) ? X[(size_t)(t - 2) * D_MODEL + d] : 0.f;
        float x1 = (t >= 1) ? X[(size_t)(t - 1) * D_MODEL + d] : 0.f;
        float x2 = X[(size_t)t * D_MODEL + d];
        float z = w[d * 3 + 0] * x0 + w[d * 3 + 1] * x1 + w[d * 3 + 2] * x2 + b[d];
        float y = z / (1.f + __expf(-z));
        vals[i] = y;
        ss += y * y;
    }
    __shared__ float red[8];
#pragma unroll
    for (int o = 16; o > 0; o >>= 1) ss += __shfl_xor_sync(0xffffffffu, ss, o);
    if ((tid & 31) == 0) red[tid >> 5] = ss;
    __syncthreads();
    if (tid < 32) {
        float v = (tid < 8) ? red[tid] : 0.f;
#pragma unroll
        for (int o = 4; o > 0; o >>= 1) v += __shfl_xor_sync(0xffffffffu, v, o);
        if (tid == 0) red[0] = v;
    }
    __syncthreads();
    float total = red[0];
    float inv = (m < 2) ? 1.f / fmaxf(sqrtf(total), 1e-12f) : 1.f;

#pragma unroll
    for (int i = 0; i < 4; i++) {
        int d = tid + i * 256;
        size_t idx = (size_t)t * D_MODEL + d;
        float y = vals[i] * inv;
        if (m == 0)      g_Qh[idx] = __float2half(y);
        else if (m == 1) g_Kh[idx] = __float2half(y);
        else {
            __half h = __float2half(y);
            g_Vh[idx] = h;
            g_Vl[idx] = __float2half(y - __half2float(h));
        }
    }
}

// ---------------- tensor-core attention ----------------
// Block = one (head, 64-query tile); 4 warps x 16 queries.
// Slots: 0-3 persistent, 4..194 window keys [q0-127, q0+63], padded to 208.
// Streaming softmax (scores bounded: no max subtraction), P frag = converted acc.
#define ASLOT 208
#define AQ    64
#define AT_QO 0
#define AT_KO 8192
#define AT_VH (8192 + 26624)
#define AT_VL (8192 + 2 * 26624)
#define ATTN_SMEM (8192 + 3 * 26624)

__global__ void __launch_bounds__(128, 2) attn_tc_kernel()
{
    extern __shared__ __align__(1024) char smc[];
    uint32_t sb = smem_u32(smc);
    int tid = threadIdx.x;
    int lane = tid & 31, w = tid >> 5;
    int h = blockIdx.x, tile = blockIdx.y;
    int q0 = NP + tile * AQ;
    int kmin = q0 - (WIN - 1);
    int hoff = h * HD;

    // ---- stage Q (64x64) ----
    for (int i = tid; i < 512; i += 128) {
        int r = i >> 3, c = i & 7;
        uint4 v = *(const uint4*)(g_Qh + (size_t)(q0 + r) * D_MODEL + hoff + c * 8);
        *(uint4*)(smc + AT_QO + r * 128 + ((c * 16) ^ ((r & 7) << 4))) = v;
    }
    // ---- stage K, Vh, Vl. FIX: clamp applies ONLY to window slots; persistent
    // slots 0-3 must read keys 0-3 (previous round clamped them to row 4). ----
    for (int i = tid; i < ASLOT * 8; i += 128) {
        int s = i >> 3, c = i & 7;
        int key = (s < 4) ? s : min(max(kmin + s - 4, NP), T_TOT - 1);
        size_t gidx = (size_t)key * D_MODEL + hoff + c * 8;
        uint32_t off = s * 128 + ((c * 16) ^ ((s & 7) << 4));
        *(uint4*)(smc + AT_KO + off) = *(const uint4*)(g_Kh + gidx);
        *(uint4*)(smc + AT_VH + off) = *(const uint4*)(g_Vh + gidx);
        *(uint4*)(smc + AT_VL + off) = *(const uint4*)(g_Vl + gidx);
    }
    __syncthreads();

    // ---- per-warp Q fragments (rows 16w..16w+15, k=64) ----
    uint32_t qf[4][4];
    {
        int ar = 16 * w + (lane & 15);
        uint32_t base = sb + AT_QO + ar * 128;
        uint32_t sw = (ar & 7) << 4;
        int ak = (lane >> 4) * 16;
#pragma unroll
        for (int ks = 0; ks < 4; ks++)
            LDSM4(qf[ks][0], qf[ks][1], qf[ks][2], qf[ks][3],
                  base + ((ks * 32 + ak) ^ sw));
    }

    int qrow0 = q0 + 16 * w + (lane >> 2);   // acc rows: qrow0, qrow0+8
    int ccol = (lane & 3) * 2;

    float o[8][4];
#pragma unroll
    for (int n = 0; n < 8; n++)
#pragma unroll
        for (int j = 0; j < 4; j++) o[n][j] = 0.f;
    float l0 = 0.f, l1 = 0.f;

    int krel = (lane & 7) + ((lane >> 4) << 3);
    int kb2 = ((lane >> 3) & 1) * 16;
    int vrel = lane & 15;

    auto process_block = [&](int bi) {
        int sbase_slot = bi * 16;
        float s0[4] = {0.f, 0.f, 0.f, 0.f}, s1[4] = {0.f, 0.f, 0.f, 0.f};
        {
            int r = sbase_slot + krel;
            uint32_t base = sb + AT_KO + r * 128;
            uint32_t sw = (r & 7) << 4;
#pragma unroll
            for (int ks = 0; ks < 4; ks++) {
                uint32_t b0, b1, b2, b3;
                LDSM4(b0, b1, b2, b3, base + ((ks * 32 + kb2) ^ sw));
                MMA16816(s0, qf[ks][0], qf[ks][1], qf[ks][2], qf[ks][3], b0, b1);
                MMA16816(s1, qf[ks][0], qf[ks][1], qf[ks][2], qf[ks][3], b2, b3);
            }
        }
        float p[8];
#pragma unroll
        for (int e = 0; e < 8; e++) {
            int tilen = e >> 2;
            int j = e & 3;
            int slot = sbase_slot + tilen * 8 + ccol + (j & 1);
            int qr = (j < 2) ? qrow0 : qrow0 + 8;
            float sc = tilen ? s1[j] : s0[j];
            int k = slot < 4 ? slot : kmin + slot - 4;
            bool valid = (slot < 4) | ((k >= NP) & (k <= qr) & (k > qr - WIN));
            p[e] = valid ? __expf(sc * 0.125f) : 0.f;
        }
        l0 += p[0] + p[1] + p[4] + p[5];
        l1 += p[2] + p[3] + p[6] + p[7];
        uint32_t a0 = pack2h(p[0], p[1]);
        uint32_t a1 = pack2h(p[2], p[3]);
        uint32_t a2 = pack2h(p[4], p[5]);
        uint32_t a3 = pack2h(p[6], p[7]);
        {
            int r = sbase_slot + vrel;
            uint32_t swv = (r & 7) << 4;
            uint32_t bh = sb + AT_VH + r * 128;
            uint32_t bl = sb + AT_VL + r * 128;
#pragma unroll
            for (int nt = 0; nt < 8; nt++) {
                uint32_t off = (nt * 16) ^ swv;
                uint32_t v0, v1;
                LDSM2T(v0, v1, bh + off);
                MMA16816(o[nt], a0, a1, a2, a3, v0, v1);
                LDSM2T(v0, v1, bl + off);
                MMA16816(o[nt], a0, a1, a2, a3, v0, v1);
            }
        }
    };

    process_block(0);
    int b_lo = (w == 0) ? 1 : w;
    int b_hi = w + 9;
    for (int bi = b_lo; bi <= b_hi; bi++) process_block(bi);

    l0 += __shfl_xor_sync(0xffffffffu, l0, 1);
    l0 += __shfl_xor_sync(0xffffffffu, l0, 2);
    l1 += __shfl_xor_sync(0xffffffffu, l1, 1);
    l1 += __shfl_xor_sync(0xffffffffu, l1, 2);
    float inv0 = 1.f / l0, inv1 = 1.f / l1;

    size_t r0 = (size_t)(qrow0 - NP) * D_MODEL + hoff + ccol;
    size_t r1 = r0 + 8 * D_MODEL;
#pragma unroll
    for (int nt = 0; nt < 8; nt++) {
        float a = o[nt][0] * inv0, b = o[nt][1] * inv0;
        float c = o[nt][2] * inv1, d = o[nt][3] * inv1;
        __half ha = __float2half(a), hb = __float2half(b);
        __half hc = __float2half(c), hd = __float2half(d);
        *(uint32_t*)(&g_at_h[r0 + nt * 8]) = (uint32_t)__half_as_ushort(ha) | ((uint32_t)__half_as_ushort(hb) << 16);
        *(uint32_t*)(&g_at_h[r1 + nt * 8]) = (uint32_t)__half_as_ushort(hc) | ((uint32_t)__half_as_ushort(hd) << 16);
        __half la = __float2half(a - __half2float(ha)), lb = __float2half(b - __half2float(hb));
        __half lc = __float2half(c - __half2float(hc)), ld = __float2half(d - __half2float(hd));
        *(uint32_t*)(&g_at_l[r0 + nt * 8]) = (uint32_t)__half_as_ushort(la) | ((uint32_t)__half_as_ushort(lb) << 16);
        *(uint32_t*)(&g_at_l[r1 + nt * 8]) = (uint32_t)__half_as_ushort(lc) | ((uint32_t)__half_as_ushort(ld) << 16);
    }
}

// ---------------- launch ----------------
extern "C" void kernel_launch(void* const* d_in, const int* in_sizes, int n_in,
                              void* d_out, int out_size)
{
    (void)in_sizes; (void)n_in; (void)out_size;
    const float* x  = (const float*)d_in[0];
    const float* pm = (const float*)d_in[1];
    const float* Wq = (const float*)d_in[2];
    const float* Wk = (const float*)d_in[3];
    const float* Wv = (const float*)d_in[4];
    const float* Wo = (const float*)d_in[5];
    const float* qw = (const float*)d_in[6];
    const float* qb = (const float*)d_in[7];
    const float* kw = (const float*)d_in[8];
    const float* kb = (const float*)d_in[9];
    const float* vw = (const float*)d_in[10];
    const float* vb = (const float*)d_in[11];
    float* out = (float*)d_out;

    cudaFuncSetAttribute(attn_tc_kernel, cudaFuncAttributeMaxDynamicSharedMemorySize, ATTN_SMEM);
    cudaFuncSetAttribute(gemm_qkv_tc, cudaFuncAttributeMaxDynamicSharedMemorySize, GEMM_SMEM);
    cudaFuncSetAttribute(gemm_out_tc, cudaFuncAttributeMaxDynamicSharedMemorySize, GEMM_SMEM);

    convert_w_kernel<<<dim3(D_MODEL * D_MODEL / 1024, 4), 256>>>(Wq, Wk, Wv, Wo);
    convert_xp_kernel<<<MPAD * D_MODEL / 1024, 256>>>(pm, x);

    gemm_qkv_tc<<<dim3(8, 17, 3), 256, GEMM_SMEM>>>();

    conv_silu_norm_kernel<<<dim3(T_TOT, 3), 256>>>(qw, qb, kw, kb, vw, vb);

    attn_tc_kernel<<<dim3(NHEADS, L_SEQ / AQ), 128, ATTN_SMEM>>>();

    gemm_out_tc<<<dim3(8, 16, 1), 256, GEMM_SMEM>>>(out);
}

// round 8
// speedup vs baseline: 7.1405x; 1.9977x over previous
#include <cuda_runtime.h>
#include <cuda_fp16.h>
#include <math.h>
#include <stdint.h>

#define D_MODEL 1024
#define T_TOT   2052
#define MPAD    2176   // 17*128
#define L_SEQ   2048
#define NP      4
#define NHEADS  16
#define HD      64
#define WIN     128

// ---------------- scratch (device globals: allocation-free) ----------------
__device__ float g_QKV[3][T_TOT * D_MODEL];   // pre-conv Q,K,V (fp32, GEMM out)
__device__ __half g_Qh[T_TOT * D_MODEL];      // post conv+silu+norm, fp16
__device__ __half g_Kh[T_TOT * D_MODEL];
__device__ __half g_Vh[T_TOT * D_MODEL];
__device__ __half g_xp_h[MPAD * D_MODEL];     // input (pm;x) fp16
__device__ __half g_w_h[4][D_MODEL * D_MODEL];// weights fp16
__device__ __half g_at_h[L_SEQ * D_MODEL];    // attention output fp16

// ---------------- helpers ----------------
__device__ __forceinline__ uint32_t smem_u32(const void* p) {
    uint32_t a;
    asm("{ .reg .u64 t; cvta.to.shared.u64 t, %1; cvt.u32.u64 %0, t; }" : "=r"(a) : "l"(p));
    return a;
}

#define LDSM4(R0, R1, R2, R3, ADDR) \
    asm volatile("ldmatrix.sync.aligned.m8n8.x4.shared.b16 {%0,%1,%2,%3}, [%4];" \
                 : "=r"(R0), "=r"(R1), "=r"(R2), "=r"(R3) : "r"(ADDR))

#define LDSM2T(R0, R1, ADDR) \
    asm volatile("ldmatrix.sync.aligned.m8n8.x2.trans.shared.b16 {%0,%1}, [%2];" \
                 : "=r"(R0), "=r"(R1) : "r"(ADDR))

#define MMA16816(D, A0, A1, A2, A3, B0, B1) \
    asm volatile("mma.sync.aligned.m16n8k16.row.col.f32.f16.f16.f32 " \
                 "{%0,%1,%2,%3}, {%4,%5,%6,%7}, {%8,%9}, {%0,%1,%2,%3};" \
                 : "+f"((D)[0]), "+f"((D)[1]), "+f"((D)[2]), "+f"((D)[3]) \
                 : "r"(A0), "r"(A1), "r"(A2), "r"(A3), "r"(B0), "r"(B1))

#define CP_ASYNC16(S, G) \
    asm volatile("cp.async.cg.shared.global [%0], [%1], 16;" :: "r"(S), "l"(G))
#define CP_COMMIT()  asm volatile("cp.async.commit_group;" ::: "memory")
#define CP_WAIT2()   asm volatile("cp.async.wait_group 2;" ::: "memory")

__device__ __forceinline__ uint32_t pack2h(float a, float b) {
    __half2 h = __floats2half2_rn(a, b);
    return *(uint32_t*)&h;
}
__device__ __forceinline__ uint2 cvt4h(float4 v) {
    uint2 r;
    r.x = pack2h(v.x, v.y);
    r.y = pack2h(v.z, v.w);
    return r;
}

// weights -> fp16
__global__ void __launch_bounds__(256) convert_w_kernel(const float* __restrict__ Wq,
                                                        const float* __restrict__ Wk,
                                                        const float* __restrict__ Wv,
                                                        const float* __restrict__ Wo)
{
    int w = blockIdx.y;
    const float* src = (w == 0) ? Wq : (w == 1) ? Wk : (w == 2) ? Wv : Wo;
    int i = (blockIdx.x * 256 + threadIdx.x) * 4;
    *(uint2*)(&g_w_h[w][i]) = cvt4h(*(const float4*)(src + i));
}

// xp = [pm(4); x(2048); pad zeros to 2176] -> fp16
__global__ void __launch_bounds__(256) convert_xp_kernel(const float* __restrict__ pm,
                                                         const float* __restrict__ x)
{
    int i = (blockIdx.x * 256 + threadIdx.x) * 4;
    int row = i >> 10, col = i & 1023;
    float4 v = make_float4(0.f, 0.f, 0.f, 0.f);
    if (row < NP)          v = *(const float4*)(pm + row * D_MODEL + col);
    else if (row < T_TOT)  v = *(const float4*)(x + (size_t)(row - NP) * D_MODEL + col);
    *(uint2*)(&g_xp_h[i]) = cvt4h(v);
}

// ---------------- mma.sync GEMM (single-pass fp16): C[128,128] = A @ B^T ----
// Stage: Ah(16K) + Bh(16K) = 32KB; 3 stages = 96KB; 2 CTAs/SM.
#define GEMM_SMEM (3 * 32768)

__device__ __forceinline__ void gemm128_body(const __half* __restrict__ Ah,
                                             const __half* __restrict__ Bh,
                                             float* __restrict__ C, int Mrows)
{
    extern __shared__ __align__(1024) char sm[];
    uint32_t sbase = smem_u32(sm);
    int tid = threadIdx.x;
    int lane = tid & 31, wid = tid >> 5;
    int bm = blockIdx.y, bn = blockIdx.x;

    const __half* srcA = Ah + (size_t)bm * 128 * D_MODEL;
    const __half* srcB = Bh + (size_t)bn * 128 * D_MODEL;

    // 2048 16B chunks per stage (A:1024, B:1024); 8 per thread
    auto issue_chunk = [&](int kc, int s) {
        uint32_t stage = sbase + s * 32768;
#pragma unroll
        for (int it = 0; it < 8; it++) {
            int g = it * 256 + tid;
            int mat = g >> 10;
            int r = (g & 1023) >> 3;
            int c = g & 7;
            const __half* gp = (mat ? srcB : srcA) + (size_t)r * D_MODEL + kc * 64 + c * 8;
            uint32_t so = stage + mat * 16384 + r * 128 + ((c * 16) ^ ((r & 7) << 4));
            CP_ASYNC16(so, gp);
        }
    };

    int m_base = (wid & 3) * 32;
    int n_base = (wid >> 2) * 64;

    int arow0 = m_base + (lane & 15);
    int ak2 = ((lane >> 4) * 8) * 2;
    int brow0 = n_base + (lane & 7) + ((lane >> 4) << 3);
    int bk2 = (((lane >> 3) & 1) * 8) * 2;

    uint32_t aoffs[2], asw[2], boffs[4], bsw[4];
#pragma unroll
    for (int mi = 0; mi < 2; mi++) {
        int r = arow0 + mi * 16;
        aoffs[mi] = r * 128; asw[mi] = (r & 7) << 4;
    }
#pragma unroll
    for (int p = 0; p < 4; p++) {
        int r = brow0 + p * 16;
        boffs[p] = r * 128; bsw[p] = (r & 7) << 4;
    }

    float acc[2][8][4];
#pragma unroll
    for (int mi = 0; mi < 2; mi++)
#pragma unroll
        for (int n = 0; n < 8; n++)
#pragma unroll
            for (int j = 0; j < 4; j++) acc[mi][n][j] = 0.f;

    issue_chunk(0, 0); CP_COMMIT();
    issue_chunk(1, 1); CP_COMMIT();
    issue_chunk(2, 2); CP_COMMIT();

    for (int kc = 0; kc < 16; kc++) {
        CP_WAIT2();
        __syncthreads();
        uint32_t stage = sbase + (kc % 3) * 32768;
        uint32_t AH = stage, BH = stage + 16384;
#pragma unroll
        for (int ks = 0; ks < 4; ks++) {
            uint32_t kb2 = ks * 32;
            uint32_t ah[2][4];
#pragma unroll
            for (int mi = 0; mi < 2; mi++)
                LDSM4(ah[mi][0], ah[mi][1], ah[mi][2], ah[mi][3],
                      AH + aoffs[mi] + ((kb2 + ak2) ^ asw[mi]));
#pragma unroll
            for (int p = 0; p < 4; p++) {
                uint32_t bh[4];
                LDSM4(bh[0], bh[1], bh[2], bh[3], BH + boffs[p] + ((kb2 + bk2) ^ bsw[p]));
#pragma unroll
                for (int mi = 0; mi < 2; mi++) {
                    MMA16816(acc[mi][2 * p],     ah[mi][0], ah[mi][1], ah[mi][2], ah[mi][3], bh[0], bh[1]);
                    MMA16816(acc[mi][2 * p + 1], ah[mi][0], ah[mi][1], ah[mi][2], ah[mi][3], bh[2], bh[3]);
                }
            }
        }
        __syncthreads();
        int c3 = kc + 3;
        if (c3 < 16) issue_chunk(c3, c3 % 3);
        CP_COMMIT();
    }

    int crow = lane >> 2;
    int ccol = (lane & 3) * 2;
#pragma unroll
    for (int mi = 0; mi < 2; mi++) {
#pragma unroll
        for (int n = 0; n < 8; n++) {
            int row0 = bm * 128 + m_base + mi * 16 + crow;
            int col = bn * 128 + n_base + n * 8 + ccol;
            if (row0 < Mrows)
                *(float2*)(C + (size_t)row0 * D_MODEL + col) = make_float2(acc[mi][n][0], acc[mi][n][1]);
            int row1 = row0 + 8;
            if (row1 < Mrows)
                *(float2*)(C + (size_t)row1 * D_MODEL + col) = make_float2(acc[mi][n][2], acc[mi][n][3]);
        }
    }
}

__global__ void __launch_bounds__(256, 2) gemm_qkv_tc(void)
{
    int z = blockIdx.z;
    gemm128_body(g_xp_h, g_w_h[z], g_QKV[z], T_TOT);
}
__global__ void __launch_bounds__(256, 2) gemm_out_tc(float* __restrict__ out)
{
    gemm128_body(g_at_h, g_w_h[3], out, L_SEQ);
}

// ---------------- fused conv(k=3) + bias + SiLU + (L2 norm) -> fp16 ----
// Block = (m, 4 consecutive timesteps); 256 threads, 4 d-columns each.
__global__ void __launch_bounds__(256) conv_silu_norm_kernel(const float* __restrict__ qw,
                                                             const float* __restrict__ qb,
                                                             const float* __restrict__ kw,
                                                             const float* __restrict__ kb,
                                                             const float* __restrict__ vw,
                                                             const float* __restrict__ vb)
{
    int m = blockIdx.y;
    int t0 = blockIdx.x * 4;
    const float* w = (m == 0) ? qw : (m == 1) ? kw : vw;
    const float* b = (m == 0) ? qb : (m == 1) ? kb : vb;
    const float* X = g_QKV[m];
    int tid = threadIdx.x;
    int d4 = tid * 4;

    float w0[4], w1[4], w2[4], bb[4];
#pragma unroll
    for (int j = 0; j < 4; j++) {
        w0[j] = w[(d4 + j) * 3 + 0];
        w1[j] = w[(d4 + j) * 3 + 1];
        w2[j] = w[(d4 + j) * 3 + 2];
        bb[j] = b[d4 + j];
    }

    float xr[6][4];
#pragma unroll
    for (int i = 0; i < 6; i++) {
        int t = t0 - 2 + i;
        if (t >= 0) {
            float4 v = *(const float4*)(X + (size_t)t * D_MODEL + d4);
            xr[i][0] = v.x; xr[i][1] = v.y; xr[i][2] = v.z; xr[i][3] = v.w;
        } else {
            xr[i][0] = xr[i][1] = xr[i][2] = xr[i][3] = 0.f;
        }
    }

    float y[4][4];
    float ss[4] = {0.f, 0.f, 0.f, 0.f};
#pragma unroll
    for (int tt = 0; tt < 4; tt++) {
#pragma unroll
        for (int j = 0; j < 4; j++) {
            float z = w0[j] * xr[tt][j] + w1[j] * xr[tt + 1][j] + w2[j] * xr[tt + 2][j] + bb[j];
            float yv = z / (1.f + __expf(-z));
            y[tt][j] = yv;
            ss[tt] += yv * yv;
        }
    }

    __shared__ float red[4][8];
#pragma unroll
    for (int o = 16; o > 0; o >>= 1) {
#pragma unroll
        for (int tt = 0; tt < 4; tt++) ss[tt] += __shfl_xor_sync(0xffffffffu, ss[tt], o);
    }
    if ((tid & 31) == 0) {
#pragma unroll
        for (int tt = 0; tt < 4; tt++) red[tt][tid >> 5] = ss[tt];
    }
    __syncthreads();
    float inv[4];
#pragma unroll
    for (int tt = 0; tt < 4; tt++) {
        float total = red[tt][0] + red[tt][1] + red[tt][2] + red[tt][3]
                    + red[tt][4] + red[tt][5] + red[tt][6] + red[tt][7];
        inv[tt] = (m < 2) ? 1.f / fmaxf(sqrtf(total), 1e-12f) : 1.f;
    }

    __half* dst = (m == 0) ? g_Qh : (m == 1) ? g_Kh : g_Vh;
#pragma unroll
    for (int tt = 0; tt < 4; tt++) {
        uint2 hv = cvt4h(make_float4(y[tt][0] * inv[tt], y[tt][1] * inv[tt],
                                     y[tt][2] * inv[tt], y[tt][3] * inv[tt]));
        *(uint2*)(dst + (size_t)(t0 + tt) * D_MODEL + d4) = hv;
    }
}

// ---------------- tensor-core attention ----------------
// Block = one (head, 64-query tile); 4 warps x 16 queries.
// Slots: 0-3 persistent, 4..194 window keys [q0-127, q0+63], padded to 208.
#define ASLOT 208
#define AQ    64
#define AT_QO 0
#define AT_KO 8192
#define AT_VH (8192 + 26624)
#define ATTN_SMEM (8192 + 2 * 26624)

__global__ void __launch_bounds__(128, 3) attn_tc_kernel()
{
    extern __shared__ __align__(1024) char smc[];
    uint32_t sb = smem_u32(smc);
    int tid = threadIdx.x;
    int lane = tid & 31, w = tid >> 5;
    int h = blockIdx.x, tile = blockIdx.y;
    int q0 = NP + tile * AQ;
    int kmin = q0 - (WIN - 1);
    int hoff = h * HD;

    // ---- stage Q (64x64) ----
    for (int i = tid; i < 512; i += 128) {
        int r = i >> 3, c = i & 7;
        uint4 v = *(const uint4*)(g_Qh + (size_t)(q0 + r) * D_MODEL + hoff + c * 8);
        *(uint4*)(smc + AT_QO + r * 128 + ((c * 16) ^ ((r & 7) << 4))) = v;
    }
    // ---- stage K, V (clamp only window slots; persistent slots read keys 0-3) ----
    for (int i = tid; i < ASLOT * 8; i += 128) {
        int s = i >> 3, c = i & 7;
        int key = (s < 4) ? s : min(max(kmin + s - 4, NP), T_TOT - 1);
        size_t gidx = (size_t)key * D_MODEL + hoff + c * 8;
        uint32_t off = s * 128 + ((c * 16) ^ ((s & 7) << 4));
        *(uint4*)(smc + AT_KO + off) = *(const uint4*)(g_Kh + gidx);
        *(uint4*)(smc + AT_VH + off) = *(const uint4*)(g_Vh + gidx);
    }
    __syncthreads();

    // ---- per-warp Q fragments (rows 16w..16w+15, k=64) ----
    uint32_t qf[4][4];
    {
        int ar = 16 * w + (lane & 15);
        uint32_t base = sb + AT_QO + ar * 128;
        uint32_t sw = (ar & 7) << 4;
        int ak = (lane >> 4) * 16;
#pragma unroll
        for (int ks = 0; ks < 4; ks++)
            LDSM4(qf[ks][0], qf[ks][1], qf[ks][2], qf[ks][3],
                  base + ((ks * 32 + ak) ^ sw));
    }

    int qrow0 = q0 + 16 * w + (lane >> 2);
    int ccol = (lane & 3) * 2;

    float o[8][4];
#pragma unroll
    for (int n = 0; n < 8; n++)
#pragma unroll
        for (int j = 0; j < 4; j++) o[n][j] = 0.f;
    float l0 = 0.f, l1 = 0.f;

    int krel = (lane & 7) + ((lane >> 4) << 3);
    int kb2 = ((lane >> 3) & 1) * 16;
    int vrel = lane & 15;

    auto process_block = [&](int bi) {
        int sbase_slot = bi * 16;
        float s0[4] = {0.f, 0.f, 0.f, 0.f}, s1[4] = {0.f, 0.f, 0.f, 0.f};
        {
            int r = sbase_slot + krel;
            uint32_t base = sb + AT_KO + r * 128;
            uint32_t sw = (r & 7) << 4;
#pragma unroll
            for (int ks = 0; ks < 4; ks++) {
                uint32_t b0, b1, b2, b3;
                LDSM4(b0, b1, b2, b3, base + ((ks * 32 + kb2) ^ sw));
                MMA16816(s0, qf[ks][0], qf[ks][1], qf[ks][2], qf[ks][3], b0, b1);
                MMA16816(s1, qf[ks][0], qf[ks][1], qf[ks][2], qf[ks][3], b2, b3);
            }
        }
        float p[8];
#pragma unroll
        for (int e = 0; e < 8; e++) {
            int tilen = e >> 2;
            int j = e & 3;
            int slot = sbase_slot + tilen * 8 + ccol + (j & 1);
            int qr = (j < 2) ? qrow0 : qrow0 + 8;
            float sc = tilen ? s1[j] : s0[j];
            int k = slot < 4 ? slot : kmin + slot - 4;
            bool valid = (slot < 4) | ((k >= NP) & (k <= qr) & (k > qr - WIN));
            p[e] = valid ? __expf(sc * 0.125f) : 0.f;
        }
        l0 += p[0] + p[1] + p[4] + p[5];
        l1 += p[2] + p[3] + p[6] + p[7];
        uint32_t a0 = pack2h(p[0], p[1]);
        uint32_t a1 = pack2h(p[2], p[3]);
        uint32_t a2 = pack2h(p[4], p[5]);
        uint32_t a3 = pack2h(p[6], p[7]);
        {
            int r = sbase_slot + vrel;
            uint32_t swv = (r & 7) << 4;
            uint32_t bh = sb + AT_VH + r * 128;
#pragma unroll
            for (int nt = 0; nt < 8; nt++) {
                uint32_t v0, v1;
                LDSM2T(v0, v1, bh + ((nt * 16) ^ swv));
                MMA16816(o[nt], a0, a1, a2, a3, v0, v1);
            }
        }
    };

    process_block(0);
    int b_lo = (w == 0) ? 1 : w;
    int b_hi = w + 9;
    for (int bi = b_lo; bi <= b_hi; bi++) process_block(bi);

    l0 += __shfl_xor_sync(0xffffffffu, l0, 1);
    l0 += __shfl_xor_sync(0xffffffffu, l0, 2);
    l1 += __shfl_xor_sync(0xffffffffu, l1, 1);
    l1 += __shfl_xor_sync(0xffffffffu, l1, 2);
    float inv0 = 1.f / l0, inv1 = 1.f / l1;

    size_t r0 = (size_t)(qrow0 - NP) * D_MODEL + hoff + ccol;
    size_t r1 = r0 + 8 * D_MODEL;
#pragma unroll
    for (int nt = 0; nt < 8; nt++) {
        *(uint32_t*)(&g_at_h[r0 + nt * 8]) = pack2h(o[nt][0] * inv0, o[nt][1] * inv0);
        *(uint32_t*)(&g_at_h[r1 + nt * 8]) = pack2h(o[nt][2] * inv1, o[nt][3] * inv1);
    }
}

// ---------------- launch ----------------
extern "C" void kernel_launch(void* const* d_in, const int* in_sizes, int n_in,
                              void* d_out, int out_size)
{
    (void)in_sizes; (void)n_in; (void)out_size;
    const float* x  = (const float*)d_in[0];
    const float* pm = (const float*)d_in[1];
    const float* Wq = (const float*)d_in[2];
    const float* Wk = (const float*)d_in[3];
    const float* Wv = (const float*)d_in[4];
    const float* Wo = (const float*)d_in[5];
    const float* qw = (const float*)d_in[6];
    const float* qb = (const float*)d_in[7];
    const float* kw = (const float*)d_in[8];
    const float* kb = (const float*)d_in[9];
    const float* vw = (const float*)d_in[10];
    const float* vb = (const float*)d_in[11];
    float* out = (float*)d_out;

    cudaFuncSetAttribute(attn_tc_kernel, cudaFuncAttributeMaxDynamicSharedMemorySize, ATTN_SMEM);
    cudaFuncSetAttribute(gemm_qkv_tc, cudaFuncAttributeMaxDynamicSharedMemorySize, GEMM_SMEM);
    cudaFuncSetAttribute(gemm_out_tc, cudaFuncAttributeMaxDynamicSharedMemorySize, GEMM_SMEM);

    convert_w_kernel<<<dim3(D_MODEL * D_MODEL / 1024, 4), 256>>>(Wq, Wk, Wv, Wo);
    convert_xp_kernel<<<MPAD * D_MODEL / 1024, 256>>>(pm, x);

    gemm_qkv_tc<<<dim3(8, 17, 3), 256, GEMM_SMEM>>>();

    conv_silu_norm_kernel<<<dim3(T_TOT / 4, 3), 256>>>(qw, qb, kw, kb, vw, vb);

    attn_tc_kernel<<<dim3(NHEADS, L_SEQ / AQ), 128, ATTN_SMEM>>>();

    gemm_out_tc<<<dim3(8, 16, 1), 256, GEMM_SMEM>>>(out);
}

// round 9
// speedup vs baseline: 7.6160x; 1.0666x over previous
#include <cuda_runtime.h>
#include <cuda_fp16.h>
#include <math.h>
#include <stdint.h>

#define D_MODEL 1024
#define T_TOT   2052
#define MPAD    2176   // 17*128
#define L_SEQ   2048
#define NP      4
#define NHEADS  16
#define HD      64
#define WIN     128

// ---------------- scratch (device globals: allocation-free) ----------------
__device__ float g_QKV[3][T_TOT * D_MODEL];   // pre-conv Q,K,V (fp32, GEMM out)
__device__ __half g_Qh[T_TOT * D_MODEL];      // post conv+silu+norm, fp16
__device__ __half g_Kh[T_TOT * D_MODEL];
__device__ __half g_Vh[T_TOT * D_MODEL];
__device__ __half g_xp_h[MPAD * D_MODEL];     // input (pm;x) fp16
__device__ __half g_w_h[4][D_MODEL * D_MODEL];// weights fp16
__device__ __half g_at_h[L_SEQ * D_MODEL];    // attention output fp16

// ---------------- helpers ----------------
__device__ __forceinline__ uint32_t smem_u32(const void* p) {
    uint32_t a;
    asm("{ .reg .u64 t; cvta.to.shared.u64 t, %1; cvt.u32.u64 %0, t; }" : "=r"(a) : "l"(p));
    return a;
}

#define LDSM4(R0, R1, R2, R3, ADDR) \
    asm volatile("ldmatrix.sync.aligned.m8n8.x4.shared.b16 {%0,%1,%2,%3}, [%4];" \
                 : "=r"(R0), "=r"(R1), "=r"(R2), "=r"(R3) : "r"(ADDR))

#define LDSM2T(R0, R1, ADDR) \
    asm volatile("ldmatrix.sync.aligned.m8n8.x2.trans.shared.b16 {%0,%1}, [%2];" \
                 : "=r"(R0), "=r"(R1) : "r"(ADDR))

#define MMA16816(D, A0, A1, A2, A3, B0, B1) \
    asm volatile("mma.sync.aligned.m16n8k16.row.col.f32.f16.f16.f32 " \
                 "{%0,%1,%2,%3}, {%4,%5,%6,%7}, {%8,%9}, {%0,%1,%2,%3};" \
                 : "+f"((D)[0]), "+f"((D)[1]), "+f"((D)[2]), "+f"((D)[3]) \
                 : "r"(A0), "r"(A1), "r"(A2), "r"(A3), "r"(B0), "r"(B1))

#define CP_ASYNC16(S, G) \
    asm volatile("cp.async.cg.shared.global [%0], [%1], 16;" :: "r"(S), "l"(G))
#define CP_COMMIT()  asm volatile("cp.async.commit_group;" ::: "memory")
#define CP_WAIT2()   asm volatile("cp.async.wait_group 2;" ::: "memory")

__device__ __forceinline__ uint32_t pack2h(float a, float b) {
    __half2 h = __floats2half2_rn(a, b);
    return *(uint32_t*)&h;
}
__device__ __forceinline__ uint2 cvt4h(float4 v) {
    uint2 r;
    r.x = pack2h(v.x, v.y);
    r.y = pack2h(v.z, v.w);
    return r;
}

// fused converts: blocks [0,4096) = weights, [4096, 4096+2176) = xp
__global__ void __launch_bounds__(256) convert_all_kernel(const float* __restrict__ pm,
                                                          const float* __restrict__ x,
                                                          const float* __restrict__ Wq,
                                                          const float* __restrict__ Wk,
                                                          const float* __restrict__ Wv,
                                                          const float* __restrict__ Wo)
{
    int bx = blockIdx.x;
    if (bx < 4096) {
        int w = bx >> 10;
        const float* src = (w == 0) ? Wq : (w == 1) ? Wk : (w == 2) ? Wv : Wo;
        int i = ((bx & 1023) * 256 + threadIdx.x) * 4;
        *(uint2*)(&g_w_h[w][i]) = cvt4h(*(const float4*)(src + i));
    } else {
        int i = ((bx - 4096) * 256 + threadIdx.x) * 4;
        int row = i >> 10, col = i & 1023;
        float4 v = make_float4(0.f, 0.f, 0.f, 0.f);
        if (row < NP)          v = *(const float4*)(pm + row * D_MODEL + col);
        else if (row < T_TOT)  v = *(const float4*)(x + (size_t)(row - NP) * D_MODEL + col);
        *(uint2*)(&g_xp_h[i]) = cvt4h(v);
    }
}

// ---------------- mma.sync GEMM: C[128,128] = A @ B^T ----------------
// 4 warps (2x2), warp tile 64x64 -> A,B fragment traffic 2x each (min for 128x128).
// Stage: Ah(16K) + Bh(16K) = 32KB; 3 stages = 96KB; 2 CTAs/SM.
#define GEMM_SMEM (3 * 32768)

__device__ __forceinline__ void gemm128_body(const __half* __restrict__ Ah,
                                             const __half* __restrict__ Bh,
                                             float* __restrict__ C, int Mrows)
{
    extern __shared__ __align__(1024) char sm[];
    uint32_t sbase = smem_u32(sm);
    int tid = threadIdx.x;
    int lane = tid & 31, wid = tid >> 5;
    int bm = blockIdx.y, bn = blockIdx.x;

    const __half* srcA = Ah + (size_t)bm * 128 * D_MODEL;
    const __half* srcB = Bh + (size_t)bn * 128 * D_MODEL;

    // 2048 16B chunks per stage (A:1024, B:1024); 16 per thread (128 thr)
    auto issue_chunk = [&](int kc, int s) {
        uint32_t stage = sbase + s * 32768;
#pragma unroll
        for (int it = 0; it < 16; it++) {
            int g = it * 128 + tid;
            int mat = g >> 10;
            int r = (g & 1023) >> 3;
            int c = g & 7;
            const __half* gp = (mat ? srcB : srcA) + (size_t)r * D_MODEL + kc * 64 + c * 8;
            uint32_t so = stage + mat * 16384 + r * 128 + ((c * 16) ^ ((r & 7) << 4));
            CP_ASYNC16(so, gp);
        }
    };

    // 2x2 warps, warp tile 64(M) x 64(N)
    int m_base = (wid & 1) * 64;
    int n_base = (wid >> 1) * 64;

    int arow0 = m_base + (lane & 15);
    int ak2 = ((lane >> 4) * 8) * 2;
    int brow0 = n_base + (lane & 7) + ((lane >> 4) << 3);
    int bk2 = (((lane >> 3) & 1) * 8) * 2;

    uint32_t aoffs[4], asw[4], boffs[4], bsw[4];
#pragma unroll
    for (int mi = 0; mi < 4; mi++) {
        int r = arow0 + mi * 16;
        aoffs[mi] = r * 128; asw[mi] = (r & 7) << 4;
    }
#pragma unroll
    for (int p = 0; p < 4; p++) {
        int r = brow0 + p * 16;
        boffs[p] = r * 128; bsw[p] = (r & 7) << 4;
    }

    float acc[4][8][4];
#pragma unroll
    for (int mi = 0; mi < 4; mi++)
#pragma unroll
        for (int n = 0; n < 8; n++)
#pragma unroll
            for (int j = 0; j < 4; j++) acc[mi][n][j] = 0.f;

    issue_chunk(0, 0); CP_COMMIT();
    issue_chunk(1, 1); CP_COMMIT();
    issue_chunk(2, 2); CP_COMMIT();

    for (int kc = 0; kc < 16; kc++) {
        CP_WAIT2();
        __syncthreads();
        uint32_t stage = sbase + (kc % 3) * 32768;
        uint32_t AH = stage, BH = stage + 16384;
#pragma unroll
        for (int ks = 0; ks < 4; ks++) {
            uint32_t kb2 = ks * 32;
            uint32_t ah[4][4];
#pragma unroll
            for (int mi = 0; mi < 4; mi++)
                LDSM4(ah[mi][0], ah[mi][1], ah[mi][2], ah[mi][3],
                      AH + aoffs[mi] + ((kb2 + ak2) ^ asw[mi]));
#pragma unroll
            for (int p = 0; p < 4; p++) {
                uint32_t bh[4];
                LDSM4(bh[0], bh[1], bh[2], bh[3], BH + boffs[p] + ((kb2 + bk2) ^ bsw[p]));
#pragma unroll
                for (int mi = 0; mi < 4; mi++) {
                    MMA16816(acc[mi][2 * p],     ah[mi][0], ah[mi][1], ah[mi][2], ah[mi][3], bh[0], bh[1]);
                    MMA16816(acc[mi][2 * p + 1], ah[mi][0], ah[mi][1], ah[mi][2], ah[mi][3], bh[2], bh[3]);
                }
            }
        }
        __syncthreads();
        int c3 = kc + 3;
        if (c3 < 16) issue_chunk(c3, c3 % 3);
        CP_COMMIT();
    }

    int crow = lane >> 2;
    int ccol = (lane & 3) * 2;
#pragma unroll
    for (int mi = 0; mi < 4; mi++) {
#pragma unroll
        for (int n = 0; n < 8; n++) {
            int row0 = bm * 128 + m_base + mi * 16 + crow;
            int col = bn * 128 + n_base + n * 8 + ccol;
            if (row0 < Mrows)
                *(float2*)(C + (size_t)row0 * D_MODEL + col) = make_float2(acc[mi][n][0], acc[mi][n][1]);
            int row1 = row0 + 8;
            if (row1 < Mrows)
                *(float2*)(C + (size_t)row1 * D_MODEL + col) = make_float2(acc[mi][n][2], acc[mi][n][3]);
        }
    }
}

__global__ void __launch_bounds__(128, 2) gemm_qkv_tc(void)
{
    int z = blockIdx.z;
    gemm128_body(g_xp_h, g_w_h[z], g_QKV[z], T_TOT);
}
__global__ void __launch_bounds__(128, 2) gemm_out_tc(float* __restrict__ out)
{
    gemm128_body(g_at_h, g_w_h[3], out, L_SEQ);
}

// ---------------- fused conv(k=3) + bias + SiLU + (L2 norm) -> fp16 ----
__global__ void __launch_bounds__(256) conv_silu_norm_kernel(const float* __restrict__ qw,
                                                             const float* __restrict__ qb,
                                                             const float* __restrict__ kw,
                                                             const float* __restrict__ kb,
                                                             const float* __restrict__ vw,
                                                             const float* __restrict__ vb)
{
    int m = blockIdx.y;
    int t0 = blockIdx.x * 4;
    const float* w = (m == 0) ? qw : (m == 1) ? kw : vw;
    const float* b = (m == 0) ? qb : (m == 1) ? kb : vb;
    const float* X = g_QKV[m];
    int tid = threadIdx.x;
    int d4 = tid * 4;

    float w0[4], w1[4], w2[4], bb[4];
#pragma unroll
    for (int j = 0; j < 4; j++) {
        w0[j] = w[(d4 + j) * 3 + 0];
        w1[j] = w[(d4 + j) * 3 + 1];
        w2[j] = w[(d4 + j) * 3 + 2];
        bb[j] = b[d4 + j];
    }

    float xr[6][4];
#pragma unroll
    for (int i = 0; i < 6; i++) {
        int t = t0 - 2 + i;
        if (t >= 0) {
            float4 v = *(const float4*)(X + (size_t)t * D_MODEL + d4);
            xr[i][0] = v.x; xr[i][1] = v.y; xr[i][2] = v.z; xr[i][3] = v.w;
        } else {
            xr[i][0] = xr[i][1] = xr[i][2] = xr[i][3] = 0.f;
        }
    }

    float y[4][4];
    float ss[4] = {0.f, 0.f, 0.f, 0.f};
#pragma unroll
    for (int tt = 0; tt < 4; tt++) {
#pragma unroll
        for (int j = 0; j < 4; j++) {
            float z = w0[j] * xr[tt][j] + w1[j] * xr[tt + 1][j] + w2[j] * xr[tt + 2][j] + bb[j];
            float yv = z / (1.f + __expf(-z));
            y[tt][j] = yv;
            ss[tt] += yv * yv;
        }
    }

    __shared__ float red[4][8];
#pragma unroll
    for (int o = 16; o > 0; o >>= 1) {
#pragma unroll
        for (int tt = 0; tt < 4; tt++) ss[tt] += __shfl_xor_sync(0xffffffffu, ss[tt], o);
    }
    if ((tid & 31) == 0) {
#pragma unroll
        for (int tt = 0; tt < 4; tt++) red[tt][tid >> 5] = ss[tt];
    }
    __syncthreads();
    float inv[4];
#pragma unroll
    for (int tt = 0; tt < 4; tt++) {
        float total = red[tt][0] + red[tt][1] + red[tt][2] + red[tt][3]
                    + red[tt][4] + red[tt][5] + red[tt][6] + red[tt][7];
        inv[tt] = (m < 2) ? 1.f / fmaxf(sqrtf(total), 1e-12f) : 1.f;
    }

    __half* dst = (m == 0) ? g_Qh : (m == 1) ? g_Kh : g_Vh;
#pragma unroll
    for (int tt = 0; tt < 4; tt++) {
        uint2 hv = cvt4h(make_float4(y[tt][0] * inv[tt], y[tt][1] * inv[tt],
                                     y[tt][2] * inv[tt], y[tt][3] * inv[tt]));
        *(uint2*)(dst + (size_t)(t0 + tt) * D_MODEL + d4) = hv;
    }
}

// ---------------- tensor-core attention ----------------
// Block = one (head, 128-query tile); 8 warps x 16 queries.
// Slots: 0-3 persistent, 4..258 window keys [q0-127, q0+127], padded to 272.
#define ASLOT 272
#define AQ    128
#define AT_QO 0
#define AT_KO 16384
#define AT_VH (16384 + 34816)
#define ATTN_SMEM (16384 + 2 * 34816)

__global__ void __launch_bounds__(256, 2) attn_tc_kernel()
{
    extern __shared__ __align__(1024) char smc[];
    uint32_t sb = smem_u32(smc);
    int tid = threadIdx.x;
    int lane = tid & 31, w = tid >> 5;
    int h = blockIdx.x, tile = blockIdx.y;
    int q0 = NP + tile * AQ;
    int kmin = q0 - (WIN - 1);
    int hoff = h * HD;

    // ---- stage Q (128x64) ----
    for (int i = tid; i < 1024; i += 256) {
        int r = i >> 3, c = i & 7;
        uint4 v = *(const uint4*)(g_Qh + (size_t)(q0 + r) * D_MODEL + hoff + c * 8);
        *(uint4*)(smc + AT_QO + r * 128 + ((c * 16) ^ ((r & 7) << 4))) = v;
    }
    // ---- stage K, V (clamp only window slots) ----
    for (int i = tid; i < ASLOT * 8; i += 256) {
        int s = i >> 3, c = i & 7;
        int key = (s < 4) ? s : min(max(kmin + s - 4, NP), T_TOT - 1);
        size_t gidx = (size_t)key * D_MODEL + hoff + c * 8;
        uint32_t off = s * 128 + ((c * 16) ^ ((s & 7) << 4));
        *(uint4*)(smc + AT_KO + off) = *(const uint4*)(g_Kh + gidx);
        *(uint4*)(smc + AT_VH + off) = *(const uint4*)(g_Vh + gidx);
    }
    __syncthreads();

    // ---- per-warp Q fragments (rows 16w..16w+15, k=64) ----
    uint32_t qf[4][4];
    {
        int ar = 16 * w + (lane & 15);
        uint32_t base = sb + AT_QO + ar * 128;
        uint32_t sw = (ar & 7) << 4;
        int ak = (lane >> 4) * 16;
#pragma unroll
        for (int ks = 0; ks < 4; ks++)
            LDSM4(qf[ks][0], qf[ks][1], qf[ks][2], qf[ks][3],
                  base + ((ks * 32 + ak) ^ sw));
    }

    int qrow0 = q0 + 16 * w + (lane >> 2);
    int ccol = (lane & 3) * 2;

    float o[8][4];
#pragma unroll
    for (int n = 0; n < 8; n++)
#pragma unroll
        for (int j = 0; j < 4; j++) o[n][j] = 0.f;
    float l0 = 0.f, l1 = 0.f;

    int krel = (lane & 7) + ((lane >> 4) << 3);
    int kb2 = ((lane >> 3) & 1) * 16;
    int vrel = lane & 15;

    auto process_block = [&](int bi) {
        int sbase_slot = bi * 16;
        float s0[4] = {0.f, 0.f, 0.f, 0.f}, s1[4] = {0.f, 0.f, 0.f, 0.f};
        {
            int r = sbase_slot + krel;
            uint32_t base = sb + AT_KO + r * 128;
            uint32_t sw = (r & 7) << 4;
#pragma unroll
            for (int ks = 0; ks < 4; ks++) {
                uint32_t b0, b1, b2, b3;
                LDSM4(b0, b1, b2, b3, base + ((ks * 32 + kb2) ^ sw));
                MMA16816(s0, qf[ks][0], qf[ks][1], qf[ks][2], qf[ks][3], b0, b1);
                MMA16816(s1, qf[ks][0], qf[ks][1], qf[ks][2], qf[ks][3], b2, b3);
            }
        }
        float p[8];
#pragma unroll
        for (int e = 0; e < 8; e++) {
            int tilen = e >> 2;
            int j = e & 3;
            int slot = sbase_slot + tilen * 8 + ccol + (j & 1);
            int qr = (j < 2) ? qrow0 : qrow0 + 8;
            float sc = tilen ? s1[j] : s0[j];
            int k = slot < 4 ? slot : kmin + slot - 4;
            bool valid = (slot < 4) | ((k >= NP) & (k <= qr) & (k > qr - WIN));
            p[e] = valid ? __expf(sc * 0.125f) : 0.f;
        }
        l0 += p[0] + p[1] + p[4] + p[5];
        l1 += p[2] + p[3] + p[6] + p[7];
        uint32_t a0 = pack2h(p[0], p[1]);
        uint32_t a1 = pack2h(p[2], p[3]);
        uint32_t a2 = pack2h(p[4], p[5]);
        uint32_t a3 = pack2h(p[6], p[7]);
        {
            int r = sbase_slot + vrel;
            uint32_t swv = (r & 7) << 4;
            uint32_t bh = sb + AT_VH + r * 128;
#pragma unroll
            for (int nt = 0; nt < 8; nt++) {
                uint32_t v0, v1;
                LDSM2T(v0, v1, bh + ((nt * 16) ^ swv));
                MMA16816(o[nt], a0, a1, a2, a3, v0, v1);
            }
        }
    };

    // block 0 (persistent + first window keys), then blocks for this warp's span
    process_block(0);
    int b_lo = (w == 0) ? 1 : w;
    int b_hi = w + 9;
    for (int bi = b_lo; bi <= b_hi; bi++) process_block(bi);

    l0 += __shfl_xor_sync(0xffffffffu, l0, 1);
    l0 += __shfl_xor_sync(0xffffffffu, l0, 2);
    l1 += __shfl_xor_sync(0xffffffffu, l1, 1);
    l1 += __shfl_xor_sync(0xffffffffu, l1, 2);
    float inv0 = 1.f / l0, inv1 = 1.f / l1;

    size_t r0 = (size_t)(qrow0 - NP) * D_MODEL + hoff + ccol;
    size_t r1 = r0 + 8 * D_MODEL;
#pragma unroll
    for (int nt = 0; nt < 8; nt++) {
        *(uint32_t*)(&g_at_h[r0 + nt * 8]) = pack2h(o[nt][0] * inv0, o[nt][1] * inv0);
        *(uint32_t*)(&g_at_h[r1 + nt * 8]) = pack2h(o[nt][2] * inv1, o[nt][3] * inv1);
    }
}

// ---------------- launch ----------------
extern "C" void kernel_launch(void* const* d_in, const int* in_sizes, int n_in,
                              void* d_out, int out_size)
{
    (void)in_sizes; (void)n_in; (void)out_size;
    const float* x  = (const float*)d_in[0];
    const float* pm = (const float*)d_in[1];
    const float* Wq = (const float*)d_in[2];
    const float* Wk = (const float*)d_in[3];
    const float* Wv = (const float*)d_in[4];
    const float* Wo = (const float*)d_in[5];
    const float* qw = (const float*)d_in[6];
    const float* qb = (const float*)d_in[7];
    const float* kw = (const float*)d_in[8];
    const float* kb = (const float*)d_in[9];
    const float* vw = (const float*)d_in[10];
    const float* vb = (const float*)d_in[11];
    float* out = (float*)d_out;

    cudaFuncSetAttribute(attn_tc_kernel, cudaFuncAttributeMaxDynamicSharedMemorySize, ATTN_SMEM);
    cudaFuncSetAttribute(gemm_qkv_tc, cudaFuncAttributeMaxDynamicSharedMemorySize, GEMM_SMEM);
    cudaFuncSetAttribute(gemm_out_tc, cudaFuncAttributeMaxDynamicSharedMemorySize, GEMM_SMEM);

    convert_all_kernel<<<4096 + MPAD, 256>>>(pm, x, Wq, Wk, Wv, Wo);

    gemm_qkv_tc<<<dim3(8, 17, 3), 128, GEMM_SMEM>>>();

    conv_silu_norm_kernel<<<dim3(T_TOT / 4, 3), 256>>>(qw, qb, kw, kb, vw, vb);

    attn_tc_kernel<<<dim3(NHEADS, L_SEQ / AQ), 256, ATTN_SMEM>>>();

    gemm_out_tc<<<dim3(8, 16, 1), 128, GEMM_SMEM>>>(out);
}